// round 14
// baseline (speedup 1.0000x reference)
#include <cuda_runtime.h>
#include <cuda_fp16.h>
#include <cstdint>

#define NN   100000
#define DD   64
#define INV  128
#define NC   40
#define NE   1600000
#define NLAY 4
#define NSB  391         // offset blocks: ceil(NN/256)
#define SWH  72          // smem stride in halves (144B = 4 banks mod 32)
#define SWI  136         // input gemm stride in halves (272B = 4 banks mod 32)
#define NTILE 1563       // ceil(NN/64)

// ---- scratch (device globals: no allocations allowed) ----
__device__ __align__(128) float  g_h[NN * DD];
__device__ __align__(128) __half g_hs16[NN * DD];   // (h * norm_src) in fp16
__device__ __align__(128) __half g_agg16[NN * DD];  // gathered agg in fp16
__device__ __align__(128) __half g_hc16[NN * DD];   // conv output in fp16
__device__ float g_norm_src[NN];
__device__ float g_norm_dst[NN];
__device__ int   g_deg_out[NN];   // out-degree counts (zeroed by offsets)
__device__ int   g_cnt[NN];       // in-degree counts  (zeroed by offsets)
__device__ int   g_row_ptr[NN];
__device__ int   g_row_end[NN];
__device__ int   g_cursor[NN];    // fully overwritten by offsets each call
__device__ int   g_col[NE];
__device__ int   g_total;         // reset by last offsets block
__device__ int   g_done;          // reset by last offsets block
__device__ float g_stats[NLAY * 2 * DD];  // slot l zeroed by gather(l) block 0

// ---------------------------------------------------------------------------
__device__ __forceinline__ void mma_f16(
        float& c0, float& c1, float& c2, float& c3,
        uint32_t a0, uint32_t a1, uint32_t a2, uint32_t a3,
        uint32_t b0, uint32_t b1) {
    asm volatile(
        "mma.sync.aligned.m16n8k16.row.col.f32.f16.f16.f32 "
        "{%0,%1,%2,%3}, {%4,%5,%6,%7}, {%8,%9}, {%0,%1,%2,%3};"
        : "+f"(c0), "+f"(c1), "+f"(c2), "+f"(c3)
        : "r"(a0), "r"(a1), "r"(a2), "r"(a3), "r"(b0), "r"(b1));
}

__device__ __forceinline__ uint32_t h2u(__half2 h) {
    return *(uint32_t*)&h;
}

// ---------------------------------------------------------------------------
__global__ void deg_kernel(const int* __restrict__ src, const int* __restrict__ dst) {
    int i = blockIdx.x * 256 + threadIdx.x;
    if (i < NE) {
        atomicAdd(&g_deg_out[src[i]], 1);
        atomicAdd(&g_cnt[dst[i]], 1);
    }
}

// Single-pass offset allocation: block-local scan + one atomicAdd per block.
// Also restores all prologue counters to zero for the next graph replay.
__global__ void offsets_kernel() {
    __shared__ int s[256];
    __shared__ int base;
    int t = threadIdx.x;
    int i = blockIdx.x * 256 + t;
    int d = 0, dout = 0;
    if (i < NN) {
        d    = g_cnt[i];      g_cnt[i] = 0;        // self-restore for replay
        dout = g_deg_out[i];  g_deg_out[i] = 0;    // self-restore for replay
    }
    s[t] = d;
    __syncthreads();
    for (int off = 1; off < 256; off <<= 1) {
        int v = (t >= off) ? s[t - off] : 0;
        __syncthreads();
        s[t] += v;
        __syncthreads();
    }
    if (t == 255) {
        base = atomicAdd(&g_total, s[255]);
        if (atomicAdd(&g_done, 1) == NSB - 1) {    // last block resets counters
            g_total = 0;
            g_done = 0;
        }
    }
    __syncthreads();
    if (i < NN) {
        int start = base + s[t] - d;
        g_row_ptr[i] = start;
        g_row_end[i] = start + d;
        g_cursor[i]  = start;
        g_norm_dst[i] = rsqrtf(fmaxf((float)d, 1.f));
        g_norm_src[i] = rsqrtf(fmaxf((float)dout, 1.f));
    }
}

__global__ void fill_kernel(const int* __restrict__ src, const int* __restrict__ dst) {
    int i = blockIdx.x * 256 + threadIdx.x;
    if (i < NE) {
        int pos = atomicAdd(&g_cursor[dst[i]], 1);
        g_col[pos] = src[i];
    }
}

// ---------------------------------------------------------------------------
// h = V @ W_in + b_in ; g_hs16 = fp16(h * norm_src).  fp16 m16n8k16 mma.
// A fragments loaded DIRECTLY from global V (no smem staging, no barriers);
// W staged once per block. 2 node-tiles per block.
__global__ void __launch_bounds__(256) input_gemm_tc(
        const float* __restrict__ V, const float* __restrict__ W,
        const float* __restrict__ b) {
    __shared__ __half Ws[DD * SWI];    // Wt[n][k] fp16, 17.4 KB (only smem)
    int tid = threadIdx.x;
    for (int q = tid; q < INV * DD / 4; q += 256) {
        int k = q >> 4, n4 = (q & 15) * 4;
        float4 w4 = ((const float4*)W)[q];
        Ws[(n4 + 0) * SWI + k] = __float2half_rn(w4.x);
        Ws[(n4 + 1) * SWI + k] = __float2half_rn(w4.y);
        Ws[(n4 + 2) * SWI + k] = __float2half_rn(w4.z);
        Ws[(n4 + 3) * SWI + k] = __float2half_rn(w4.w);
    }
    __syncthreads();
    int lane = tid & 31, warp = tid >> 5;
    int wr = warp & 3, wc = warp >> 2;
    int g = lane >> 2, tig = lane & 3;
    const float2 z2 = make_float2(0.f, 0.f);
#pragma unroll 1
    for (int t2 = 0; t2 < 2; t2++) {
        int tile = blockIdx.x * 2 + t2;
        if (tile >= NTILE) break;
        int node0 = tile * 64;
        int r1 = node0 + wr * 16 + g, r2 = r1 + 8;
        bool v1 = (r1 < NN), v2 = (r2 < NN);
        const float* vr1 = V + (size_t)r1 * INV + 2 * tig;
        const float* vr2 = V + (size_t)r2 * INV + 2 * tig;
        float c[4][4] = {};
#pragma unroll
        for (int kk = 0; kk < INV; kk += 16) {
            float2 f0 = v1 ? *(const float2*)&vr1[kk]     : z2;
            float2 f1 = v2 ? *(const float2*)&vr2[kk]     : z2;
            float2 f2 = v1 ? *(const float2*)&vr1[kk + 8] : z2;
            float2 f3 = v2 ? *(const float2*)&vr2[kk + 8] : z2;
            uint32_t a0 = h2u(__floats2half2_rn(f0.x, f0.y));
            uint32_t a1 = h2u(__floats2half2_rn(f1.x, f1.y));
            uint32_t a2 = h2u(__floats2half2_rn(f2.x, f2.y));
            uint32_t a3 = h2u(__floats2half2_rn(f3.x, f3.y));
#pragma unroll
            for (int nt = 0; nt < 4; nt++) {
                int nn = wc * 32 + nt * 8;
                uint32_t b0 = *(const uint32_t*)&Ws[(nn + g) * SWI + kk + 2 * tig];
                uint32_t b1 = *(const uint32_t*)&Ws[(nn + g) * SWI + kk + 2 * tig + 8];
                mma_f16(c[nt][0], c[nt][1], c[nt][2], c[nt][3],
                        a0, a1, a2, a3, b0, b1);
            }
        }
        float ns1 = v1 ? g_norm_src[r1] : 0.f;
        float ns2 = v2 ? g_norm_src[r2] : 0.f;
#pragma unroll
        for (int nt = 0; nt < 4; nt++) {
            int f = wc * 32 + nt * 8 + tig * 2;
            float b0 = b[f], b1 = b[f + 1];
            if (v1) {
                float x = c[nt][0] + b0, y = c[nt][1] + b1;
                *(float2*)&g_h[(size_t)r1 * DD + f] = make_float2(x, y);
                *(__half2*)&g_hs16[(size_t)r1 * DD + f] = __floats2half2_rn(x * ns1, y * ns1);
            }
            if (v2) {
                float x = c[nt][2] + b0, y = c[nt][3] + b1;
                *(float2*)&g_h[(size_t)r2 * DD + f] = make_float2(x, y);
                *(__half2*)&g_hs16[(size_t)r2 * DD + f] = __floats2half2_rn(x * ns2, y * ns2);
            }
        }
    }
}

// ---------------------------------------------------------------------------
// CSR gather segment-sum, fp16 rows, LDG.128, masked MLP-4 (near BW floor).
// Block 0 also zeroes this layer's BN stats slot (gemm runs strictly after).
#define ACC4(r) do { const __half2* _hh = (const __half2*)&(r); float2 _t;   \
    _t = __half22float2(_hh[0]); ac0.x += _t.x; ac0.y += _t.y;               \
    _t = __half22float2(_hh[1]); ac1.x += _t.x; ac1.y += _t.y;               \
    _t = __half22float2(_hh[2]); ac2.x += _t.x; ac2.y += _t.y;               \
    _t = __half22float2(_hh[3]); ac3.x += _t.x; ac3.y += _t.y; } while (0)

__global__ void __launch_bounds__(256) gather_kernel(float* __restrict__ stats) {
    int tid = threadIdx.x;
    if (blockIdx.x == 0 && tid < 2 * DD) stats[tid] = 0.f;
    int lane = tid & 31;
    int node = blockIdx.x * 8 + (tid >> 5);       // NN divisible by 8
    int group = lane >> 3;                         // 0..3
    int sub   = lane & 7;                          // 0..7
    int e0  = __ldg(&g_row_ptr[node]);
    int end = __ldg(&g_row_end[node]);
    const float4* __restrict__ hs = (const float4*)g_hs16;
    const float4 z4 = make_float4(0.f, 0.f, 0.f, 0.f);

    float2 ac0 = {0.f, 0.f}, ac1 = {0.f, 0.f}, ac2 = {0.f, 0.f}, ac3 = {0.f, 0.f};
    for (int e = e0 + group; e < end; e += 16) {
        int i1 = e + 4, i2 = e + 8, i3 = e + 12;
        int s0 = __ldg(&g_col[e]);
        int s1 = __ldg(&g_col[i1 < end ? i1 : e]);
        int s2 = __ldg(&g_col[i2 < end ? i2 : e]);
        int s3 = __ldg(&g_col[i3 < end ? i3 : e]);
        float4 r0 = hs[(size_t)s0 * 8 + sub];
        float4 r1 = hs[(size_t)s1 * 8 + sub];
        float4 r2 = hs[(size_t)s2 * 8 + sub];
        float4 r3 = hs[(size_t)s3 * 8 + sub];
        if (i1 >= end) r1 = z4;
        if (i2 >= end) r2 = z4;
        if (i3 >= end) r3 = z4;
        ACC4(r0); ACC4(r1); ACC4(r2); ACC4(r3);
    }
#pragma unroll
    for (int off = 8; off <= 16; off <<= 1) {
        ac0.x += __shfl_xor_sync(0xffffffffu, ac0.x, off);
        ac0.y += __shfl_xor_sync(0xffffffffu, ac0.y, off);
        ac1.x += __shfl_xor_sync(0xffffffffu, ac1.x, off);
        ac1.y += __shfl_xor_sync(0xffffffffu, ac1.y, off);
        ac2.x += __shfl_xor_sync(0xffffffffu, ac2.x, off);
        ac2.y += __shfl_xor_sync(0xffffffffu, ac2.y, off);
        ac3.x += __shfl_xor_sync(0xffffffffu, ac3.x, off);
        ac3.y += __shfl_xor_sync(0xffffffffu, ac3.y, off);
    }
    float nd = g_norm_dst[node];
    if (lane < 16) {
        int half = lane >> 3;
        __half2 o0, o1;
        if (half == 0) {
            o0 = __floats2half2_rn(ac0.x * nd, ac0.y * nd);
            o1 = __floats2half2_rn(ac1.x * nd, ac1.y * nd);
        } else {
            o0 = __floats2half2_rn(ac2.x * nd, ac2.y * nd);
            o1 = __floats2half2_rn(ac3.x * nd, ac3.y * nd);
        }
        __half2* op = (__half2*)&g_agg16[(size_t)node * DD + sub * 8 + half * 4];
        op[0] = o0; op[1] = o1;
    }
}

// ---------------------------------------------------------------------------
// hc16 = fp16(agg @ W + b) via fp16 mma; BN stats into stats slot.
// 2 node-tiles per block (W staged once).
__global__ void __launch_bounds__(256) gemm_bn_tc(
        const float* __restrict__ W, const float* __restrict__ bias,
        float* __restrict__ stats) {
    __shared__ __half Ws[DD * SWH];
    __shared__ __half As[64 * SWH];
    __shared__ float ssum[DD], ssq[DD];
    int tid = threadIdx.x;
    if (tid < DD) { ssum[tid] = 0.f; ssq[tid] = 0.f; }
    for (int q = tid; q < DD * DD / 4; q += 256) {
        int k = q >> 4, n4 = (q & 15) * 4;
        float4 w4 = ((const float4*)W)[q];
        Ws[(n4 + 0) * SWH + k] = __float2half_rn(w4.x);
        Ws[(n4 + 1) * SWH + k] = __float2half_rn(w4.y);
        Ws[(n4 + 2) * SWH + k] = __float2half_rn(w4.z);
        Ws[(n4 + 3) * SWH + k] = __float2half_rn(w4.w);
    }
    int lane = tid & 31, warp = tid >> 5;
    int wr = warp & 3, wc = warp >> 2;
    int g = lane >> 2, tig = lane & 3;
#pragma unroll 1
    for (int t2 = 0; t2 < 2; t2++) {
        int tile = blockIdx.x * 2 + t2;
        if (tile >= NTILE) break;
        int node0 = tile * 64;
        __syncthreads();
        for (int q = tid; q < 64 * DD / 8; q += 256) {
            int row = q >> 3, c8 = (q & 7) * 8;
            int n = node0 + row;
            int4 v = (n < NN)
                ? *(const int4*)&g_agg16[(size_t)n * DD + c8]
                : make_int4(0, 0, 0, 0);
            *(int4*)&As[row * SWH + c8] = v;
        }
        __syncthreads();
        float c[4][4] = {};
#pragma unroll
        for (int kk = 0; kk < DD; kk += 16) {
            uint32_t a0 = *(const uint32_t*)&As[(wr * 16 + g) * SWH + kk + 2 * tig];
            uint32_t a1 = *(const uint32_t*)&As[(wr * 16 + g + 8) * SWH + kk + 2 * tig];
            uint32_t a2 = *(const uint32_t*)&As[(wr * 16 + g) * SWH + kk + 2 * tig + 8];
            uint32_t a3 = *(const uint32_t*)&As[(wr * 16 + g + 8) * SWH + kk + 2 * tig + 8];
#pragma unroll
            for (int nt = 0; nt < 4; nt++) {
                int nn = wc * 32 + nt * 8;
                uint32_t b0 = *(const uint32_t*)&Ws[(nn + g) * SWH + kk + 2 * tig];
                uint32_t b1 = *(const uint32_t*)&Ws[(nn + g) * SWH + kk + 2 * tig + 8];
                mma_f16(c[nt][0], c[nt][1], c[nt][2], c[nt][3],
                        a0, a1, a2, a3, b0, b1);
            }
        }
        int r1 = node0 + wr * 16 + g, r2 = r1 + 8;
        bool v1 = (r1 < NN), v2 = (r2 < NN);
#pragma unroll
        for (int nt = 0; nt < 4; nt++) {
            int f = wc * 32 + nt * 8 + tig * 2;
            float b0 = bias[f], b1 = bias[f + 1];
            float s0 = 0.f, s1 = 0.f, q0 = 0.f, q1 = 0.f;
            if (v1) {
                float x = c[nt][0] + b0, y = c[nt][1] + b1;
                *(__half2*)&g_hc16[(size_t)r1 * DD + f] = __floats2half2_rn(x, y);
                s0 += x; s1 += y; q0 += x * x; q1 += y * y;
            }
            if (v2) {
                float x = c[nt][2] + b0, y = c[nt][3] + b1;
                *(__half2*)&g_hc16[(size_t)r2 * DD + f] = __floats2half2_rn(x, y);
                s0 += x; s1 += y; q0 += x * x; q1 += y * y;
            }
#pragma unroll
            for (int off = 4; off <= 16; off <<= 1) {
                s0 += __shfl_xor_sync(0xffffffffu, s0, off);
                s1 += __shfl_xor_sync(0xffffffffu, s1, off);
                q0 += __shfl_xor_sync(0xffffffffu, q0, off);
                q1 += __shfl_xor_sync(0xffffffffu, q1, off);
            }
            if (g == 0) {
                atomicAdd(&ssum[f], s0);     atomicAdd(&ssum[f + 1], s1);
                atomicAdd(&ssq[f], q0);      atomicAdd(&ssq[f + 1], q1);
            }
        }
    }
    __syncthreads();
    if (tid < DD) {
        atomicAdd(&stats[tid],      ssum[tid]);
        atomicAdd(&stats[DD + tid], ssq[tid]);
    }
}

// ---------------------------------------------------------------------------
// BN finalize + apply + leakyrelu + residual; write g_hs16 for next layer.
// 2 chunks per thread for ILP.
__global__ void bn_apply_kernel(const float* __restrict__ gamma,
                                const float* __restrict__ beta,
                                const float* __restrict__ stats) {
    __shared__ float sc[DD], sh[DD];
    int tid = threadIdx.x;
    if (tid < DD) {
        float mean = stats[tid] * (1.f / NN);
        float ex2  = stats[DD + tid] * (1.f / NN);
        float inv  = rsqrtf(ex2 - mean * mean + 1e-5f);
        float s    = gamma[tid] * inv;
        sc[tid] = s;
        sh[tid] = beta[tid] - mean * s;
    }
    __syncthreads();
#pragma unroll
    for (int u = 0; u < 2; u++) {
        int i = blockIdx.x * 512 + u * 256 + tid;   // over NN*16 float4s
        if (i >= NN * (DD / 4)) return;
        int n = i >> 4;
        int f0 = (i & 15) * 4;
        const __half2* cp = (const __half2*)&g_hc16[(size_t)i * 4];
        float2 c01 = __half22float2(cp[0]);
        float2 c23 = __half22float2(cp[1]);
        float4 h4 = ((const float4*)g_h)[i];
        float ns = g_norm_src[n];
        float v;
        v = c01.x * sc[f0 + 0] + sh[f0 + 0]; h4.x += (v >= 0.f) ? v : 0.2f * v;
        v = c01.y * sc[f0 + 1] + sh[f0 + 1]; h4.y += (v >= 0.f) ? v : 0.2f * v;
        v = c23.x * sc[f0 + 2] + sh[f0 + 2]; h4.z += (v >= 0.f) ? v : 0.2f * v;
        v = c23.y * sc[f0 + 3] + sh[f0 + 3]; h4.w += (v >= 0.f) ? v : 0.2f * v;
        ((float4*)g_h)[i] = h4;
        __half2* hp = (__half2*)&g_hs16[(size_t)i * 4];
        hp[0] = __floats2half2_rn(h4.x * ns, h4.y * ns);
        hp[1] = __floats2half2_rn(h4.z * ns, h4.w * ns);
    }
}

// ---------------------------------------------------------------------------
// Final fused kernel: BN(l=3)+leaky+residual, logits + log_softmax.
__global__ void __launch_bounds__(256) out_kernel(
        const float* __restrict__ gamma, const float* __restrict__ beta,
        const float* __restrict__ stats,
        const float* __restrict__ W, const float* __restrict__ b,
        float* __restrict__ out) {
    __shared__ float Ws[DD * NC];   // 10 KB
    __shared__ float bs[NC];
    __shared__ float sc[DD], sh[DD];
    __shared__ float hrow[8][DD];
    int tid = threadIdx.x;          // 256 threads = 8 warps
    for (int i = tid; i < DD * NC; i += 256) Ws[i] = W[i];
    if (tid < NC) bs[tid] = b[tid];
    if (tid < DD) {
        float mean = stats[tid] * (1.f / NN);
        float ex2  = stats[DD + tid] * (1.f / NN);
        float inv  = rsqrtf(ex2 - mean * mean + 1e-5f);
        float s    = gamma[tid] * inv;
        sc[tid] = s;
        sh[tid] = beta[tid] - mean * s;
    }
    __syncthreads();
    int warp = tid >> 5, lane = tid & 31;
    int n = blockIdx.x * 8 + warp;  // NN divisible by 8
    if (n >= NN) return;
    {
        int f = lane * 2;
        float2 c  = __half22float2(*(const __half2*)&g_hc16[(size_t)n * DD + f]);
        float2 h2 = *(const float2*)&g_h[(size_t)n * DD + f];
        float v;
        v = c.x * sc[f]     + sh[f];     h2.x += (v >= 0.f) ? v : 0.2f * v;
        v = c.y * sc[f + 1] + sh[f + 1]; h2.y += (v >= 0.f) ? v : 0.2f * v;
        hrow[warp][f]     = h2.x;
        hrow[warp][f + 1] = h2.y;
    }
    __syncwarp();
    int c0 = lane, c1 = lane + 32;
    bool has1 = (c1 < NC);
    float acc0 = bs[c0];
    float acc1 = has1 ? bs[c1] : 0.f;
#pragma unroll
    for (int k = 0; k < DD; k++) {
        float hv = hrow[warp][k];
        acc0 += hv * Ws[k * NC + c0];
        if (has1) acc1 += hv * Ws[k * NC + c1];
    }
    float m = has1 ? fmaxf(acc0, acc1) : acc0;
#pragma unroll
    for (int off = 16; off; off >>= 1) m = fmaxf(m, __shfl_xor_sync(0xffffffffu, m, off));
    float e = expf(acc0 - m) + (has1 ? expf(acc1 - m) : 0.f);
#pragma unroll
    for (int off = 16; off; off >>= 1) e += __shfl_xor_sync(0xffffffffu, e, off);
    float ls = m + logf(e);
    out[(size_t)n * NC + c0] = acc0 - ls;
    if (has1) out[(size_t)n * NC + c1] = acc1 - ls;
}

// ---------------------------------------------------------------------------
extern "C" void kernel_launch(void* const* d_in, const int* in_sizes, int n_in,
                              void* d_out, int out_size) {
    const float* V     = (const float*)d_in[0];
    const int*   src   = (const int*)d_in[1];
    const int*   dst   = (const int*)d_in[2];
    const float* W_in  = (const float*)d_in[3];
    const float* b_in  = (const float*)d_in[4];
    const float* W_l   = (const float*)d_in[5];
    const float* b_l   = (const float*)d_in[6];
    const float* gamma = (const float*)d_in[7];
    const float* beta  = (const float*)d_in[8];
    const float* W_out = (const float*)d_in[9];
    const float* b_out = (const float*)d_in[10];
    float* out = (float*)d_out;

    float* stats_base;
    cudaGetSymbolAddress((void**)&stats_base, g_stats);

    deg_kernel<<<(NE + 255) / 256, 256>>>(src, dst);
    offsets_kernel<<<NSB, 256>>>();
    fill_kernel<<<(NE + 255) / 256, 256>>>(src, dst);

    input_gemm_tc<<<(NTILE + 1) / 2, 256>>>(V, W_in, b_in);

    for (int l = 0; l < NLAY; l++) {
        float* stats = stats_base + (size_t)l * 2 * DD;
        gather_kernel<<<NN / 8, 256>>>(stats);
        gemm_bn_tc<<<(NTILE + 1) / 2, 256>>>(W_l + (size_t)l * DD * DD,
                                             b_l + (size_t)l * DD, stats);
        if (l < NLAY - 1) {
            bn_apply_kernel<<<(NN * (DD / 4) + 511) / 512, 256>>>(
                gamma + (size_t)l * DD, beta + (size_t)l * DD, stats);
        }
    }

    out_kernel<<<NN / 8, 256>>>(gamma + (size_t)(NLAY - 1) * DD,
                                beta + (size_t)(NLAY - 1) * DD,
                                stats_base + (size_t)(NLAY - 1) * 2 * DD,
                                W_out, b_out, out);
}

// round 15
// speedup vs baseline: 1.0108x; 1.0108x over previous
#include <cuda_runtime.h>
#include <cuda_fp16.h>
#include <cstdint>

#define NN   100000
#define DD   64
#define INV  128
#define NC   40
#define NE   1600000
#define NLAY 4
#define NSB  391         // offset blocks: ceil(NN/256)
#define SWH  72          // smem stride in halves (144B = 4 banks mod 32)
#define SWI  136         // input gemm stride in halves (272B = 4 banks mod 32)
#define NTILE 1563       // ceil(NN/64)

// ---- scratch (device globals: no allocations allowed) ----
__device__ __align__(128) float  g_h[NN * DD];
__device__ __align__(128) __half g_v16[NN * INV];   // V pre-converted to fp16
__device__ __align__(128) __half g_hs16[NN * DD];   // (h * norm_src) in fp16
__device__ __align__(128) __half g_agg16[NN * DD];  // gathered agg in fp16
__device__ __align__(128) __half g_hc16[NN * DD];   // conv output in fp16
__device__ float g_norm_src[NN];
__device__ float g_norm_dst[NN];
__device__ int   g_deg_out[NN];   // out-degree counts (zeroed by offsets)
__device__ int   g_cnt[NN];       // in-degree counts  (zeroed by offsets)
__device__ int   g_row_ptr[NN];
__device__ int   g_row_end[NN];
__device__ int   g_cursor[NN];    // fully overwritten by offsets each call
__device__ int   g_col[NE];
__device__ int   g_total;         // reset by last offsets block
__device__ int   g_done;          // reset by last offsets block
__device__ float g_stats[NLAY * 2 * DD];  // slot l zeroed by gather(l) block 0

// ---------------------------------------------------------------------------
__device__ __forceinline__ void mma_f16(
        float& c0, float& c1, float& c2, float& c3,
        uint32_t a0, uint32_t a1, uint32_t a2, uint32_t a3,
        uint32_t b0, uint32_t b1) {
    asm volatile(
        "mma.sync.aligned.m16n8k16.row.col.f32.f16.f16.f32 "
        "{%0,%1,%2,%3}, {%4,%5,%6,%7}, {%8,%9}, {%0,%1,%2,%3};"
        : "+f"(c0), "+f"(c1), "+f"(c2), "+f"(c3)
        : "r"(a0), "r"(a1), "r"(a2), "r"(a3), "r"(b0), "r"(b1));
}

// ---------------------------------------------------------------------------
__global__ void deg_kernel(const int* __restrict__ src, const int* __restrict__ dst) {
    int i = blockIdx.x * 256 + threadIdx.x;
    if (i < NE) {
        atomicAdd(&g_deg_out[src[i]], 1);
        atomicAdd(&g_cnt[dst[i]], 1);
    }
}

// Single-pass offset allocation: block-local scan + one atomicAdd per block.
// Also restores all prologue counters to zero for the next graph replay.
__global__ void offsets_kernel() {
    __shared__ int s[256];
    __shared__ int base;
    int t = threadIdx.x;
    int i = blockIdx.x * 256 + t;
    int d = 0, dout = 0;
    if (i < NN) {
        d    = g_cnt[i];      g_cnt[i] = 0;        // self-restore for replay
        dout = g_deg_out[i];  g_deg_out[i] = 0;    // self-restore for replay
    }
    s[t] = d;
    __syncthreads();
    for (int off = 1; off < 256; off <<= 1) {
        int v = (t >= off) ? s[t - off] : 0;
        __syncthreads();
        s[t] += v;
        __syncthreads();
    }
    if (t == 255) {
        base = atomicAdd(&g_total, s[255]);
        if (atomicAdd(&g_done, 1) == NSB - 1) {    // last block resets counters
            g_total = 0;
            g_done = 0;
        }
    }
    __syncthreads();
    if (i < NN) {
        int start = base + s[t] - d;
        g_row_ptr[i] = start;
        g_row_end[i] = start + d;
        g_cursor[i]  = start;
        g_norm_dst[i] = rsqrtf(fmaxf((float)d, 1.f));
        g_norm_src[i] = rsqrtf(fmaxf((float)dout, 1.f));
    }
}

__global__ void fill_kernel(const int* __restrict__ src, const int* __restrict__ dst) {
    int i = blockIdx.x * 256 + threadIdx.x;
    if (i < NE) {
        int pos = atomicAdd(&g_cursor[dst[i]], 1);
        g_col[pos] = src[i];
    }
}

// ---------------------------------------------------------------------------
// V fp32 -> fp16 streaming convert (coalesced, no barriers).
__global__ void v_convert_kernel(const float* __restrict__ V) {
    int i = blockIdx.x * 256 + threadIdx.x;     // over NN*INV/8 int4 chunks
    if (i >= NN * INV / 8) return;
    const float4* vp = (const float4*)V + (size_t)i * 2;
    float4 a = vp[0], b = vp[1];
    __half2 h[4];
    h[0] = __floats2half2_rn(a.x, a.y);
    h[1] = __floats2half2_rn(a.z, a.w);
    h[2] = __floats2half2_rn(b.x, b.y);
    h[3] = __floats2half2_rn(b.z, b.w);
    ((int4*)g_v16)[i] = *(const int4*)h;
}

// ---------------------------------------------------------------------------
// h = V16 @ W_in + b_in ; g_hs16 = fp16(h * norm_src).  fp16 m16n8k16 mma.
// A staged as raw fp16 int4 copies (no cvt); W staged once; 2 tiles/block.
__global__ void __launch_bounds__(256) input_gemm_tc(
        const float* __restrict__ W, const float* __restrict__ b) {
    __shared__ __half Ws[DD * SWI];    // Wt[n][k] fp16, 17.4 KB
    __shared__ __half As[64 * SWI];    // V16 tile [m][k] fp16, 17.4 KB
    int tid = threadIdx.x;
    // stage W transposed: W[k][n] fp32 -> Wt[n][k] fp16 (once per block)
    for (int q = tid; q < INV * DD / 4; q += 256) {
        int k = q >> 4, n4 = (q & 15) * 4;
        float4 w4 = ((const float4*)W)[q];
        Ws[(n4 + 0) * SWI + k] = __float2half_rn(w4.x);
        Ws[(n4 + 1) * SWI + k] = __float2half_rn(w4.y);
        Ws[(n4 + 2) * SWI + k] = __float2half_rn(w4.z);
        Ws[(n4 + 3) * SWI + k] = __float2half_rn(w4.w);
    }
    int lane = tid & 31, warp = tid >> 5;
    int wr = warp & 3, wc = warp >> 2;
    int g = lane >> 2, tig = lane & 3;
#pragma unroll 1
    for (int t2 = 0; t2 < 2; t2++) {
        int tile = blockIdx.x * 2 + t2;
        if (tile >= NTILE) break;
        int node0 = tile * 64;
        __syncthreads();
        // raw fp16 A staging: 64 rows x 128 halves, int4 = 8 halves
        for (int q = tid; q < 64 * INV / 8; q += 256) {
            int row = q >> 4, c8 = (q & 15) * 8;
            int n = node0 + row;
            int4 v = (n < NN)
                ? *(const int4*)&g_v16[(size_t)n * INV + c8]
                : make_int4(0, 0, 0, 0);
            *(int4*)&As[row * SWI + c8] = v;
        }
        __syncthreads();
        float c[4][4] = {};
#pragma unroll
        for (int kk = 0; kk < INV; kk += 16) {
            uint32_t a0 = *(const uint32_t*)&As[(wr * 16 + g) * SWI + kk + 2 * tig];
            uint32_t a1 = *(const uint32_t*)&As[(wr * 16 + g + 8) * SWI + kk + 2 * tig];
            uint32_t a2 = *(const uint32_t*)&As[(wr * 16 + g) * SWI + kk + 2 * tig + 8];
            uint32_t a3 = *(const uint32_t*)&As[(wr * 16 + g + 8) * SWI + kk + 2 * tig + 8];
#pragma unroll
            for (int nt = 0; nt < 4; nt++) {
                int nn = wc * 32 + nt * 8;
                uint32_t b0 = *(const uint32_t*)&Ws[(nn + g) * SWI + kk + 2 * tig];
                uint32_t b1 = *(const uint32_t*)&Ws[(nn + g) * SWI + kk + 2 * tig + 8];
                mma_f16(c[nt][0], c[nt][1], c[nt][2], c[nt][3],
                        a0, a1, a2, a3, b0, b1);
            }
        }
        int r1 = node0 + wr * 16 + g, r2 = r1 + 8;
        bool v1 = (r1 < NN), v2 = (r2 < NN);
        float ns1 = v1 ? g_norm_src[r1] : 0.f;
        float ns2 = v2 ? g_norm_src[r2] : 0.f;
#pragma unroll
        for (int nt = 0; nt < 4; nt++) {
            int f = wc * 32 + nt * 8 + tig * 2;
            float b0 = b[f], b1 = b[f + 1];
            if (v1) {
                float x = c[nt][0] + b0, y = c[nt][1] + b1;
                *(float2*)&g_h[(size_t)r1 * DD + f] = make_float2(x, y);
                *(__half2*)&g_hs16[(size_t)r1 * DD + f] = __floats2half2_rn(x * ns1, y * ns1);
            }
            if (v2) {
                float x = c[nt][2] + b0, y = c[nt][3] + b1;
                *(float2*)&g_h[(size_t)r2 * DD + f] = make_float2(x, y);
                *(__half2*)&g_hs16[(size_t)r2 * DD + f] = __floats2half2_rn(x * ns2, y * ns2);
            }
        }
    }
}

// ---------------------------------------------------------------------------
// CSR gather segment-sum, fp16 rows, LDG.128, masked MLP-4 (near BW floor).
// Block 0 also zeroes this layer's BN stats slot (gemm runs strictly after).
#define ACC4(r) do { const __half2* _hh = (const __half2*)&(r); float2 _t;   \
    _t = __half22float2(_hh[0]); ac0.x += _t.x; ac0.y += _t.y;               \
    _t = __half22float2(_hh[1]); ac1.x += _t.x; ac1.y += _t.y;               \
    _t = __half22float2(_hh[2]); ac2.x += _t.x; ac2.y += _t.y;               \
    _t = __half22float2(_hh[3]); ac3.x += _t.x; ac3.y += _t.y; } while (0)

__global__ void __launch_bounds__(256) gather_kernel(float* __restrict__ stats) {
    int tid = threadIdx.x;
    if (blockIdx.x == 0 && tid < 2 * DD) stats[tid] = 0.f;
    int lane = tid & 31;
    int node = blockIdx.x * 8 + (tid >> 5);       // NN divisible by 8
    int group = lane >> 3;                         // 0..3
    int sub   = lane & 7;                          // 0..7
    int e0  = __ldg(&g_row_ptr[node]);
    int end = __ldg(&g_row_end[node]);
    const float4* __restrict__ hs = (const float4*)g_hs16;
    const float4 z4 = make_float4(0.f, 0.f, 0.f, 0.f);

    float2 ac0 = {0.f, 0.f}, ac1 = {0.f, 0.f}, ac2 = {0.f, 0.f}, ac3 = {0.f, 0.f};
    for (int e = e0 + group; e < end; e += 16) {
        int i1 = e + 4, i2 = e + 8, i3 = e + 12;
        int s0 = __ldg(&g_col[e]);
        int s1 = __ldg(&g_col[i1 < end ? i1 : e]);
        int s2 = __ldg(&g_col[i2 < end ? i2 : e]);
        int s3 = __ldg(&g_col[i3 < end ? i3 : e]);
        float4 r0 = hs[(size_t)s0 * 8 + sub];
        float4 r1 = hs[(size_t)s1 * 8 + sub];
        float4 r2 = hs[(size_t)s2 * 8 + sub];
        float4 r3 = hs[(size_t)s3 * 8 + sub];
        if (i1 >= end) r1 = z4;
        if (i2 >= end) r2 = z4;
        if (i3 >= end) r3 = z4;
        ACC4(r0); ACC4(r1); ACC4(r2); ACC4(r3);
    }
#pragma unroll
    for (int off = 8; off <= 16; off <<= 1) {
        ac0.x += __shfl_xor_sync(0xffffffffu, ac0.x, off);
        ac0.y += __shfl_xor_sync(0xffffffffu, ac0.y, off);
        ac1.x += __shfl_xor_sync(0xffffffffu, ac1.x, off);
        ac1.y += __shfl_xor_sync(0xffffffffu, ac1.y, off);
        ac2.x += __shfl_xor_sync(0xffffffffu, ac2.x, off);
        ac2.y += __shfl_xor_sync(0xffffffffu, ac2.y, off);
        ac3.x += __shfl_xor_sync(0xffffffffu, ac3.x, off);
        ac3.y += __shfl_xor_sync(0xffffffffu, ac3.y, off);
    }
    float nd = g_norm_dst[node];
    if (lane < 16) {
        int half = lane >> 3;
        __half2 o0, o1;
        if (half == 0) {
            o0 = __floats2half2_rn(ac0.x * nd, ac0.y * nd);
            o1 = __floats2half2_rn(ac1.x * nd, ac1.y * nd);
        } else {
            o0 = __floats2half2_rn(ac2.x * nd, ac2.y * nd);
            o1 = __floats2half2_rn(ac3.x * nd, ac3.y * nd);
        }
        __half2* op = (__half2*)&g_agg16[(size_t)node * DD + sub * 8 + half * 4];
        op[0] = o0; op[1] = o1;
    }
}

// ---------------------------------------------------------------------------
// hc16 = fp16(agg @ W + b) via fp16 mma; BN stats into stats slot.
// 2 node-tiles per block (W staged once).
__global__ void __launch_bounds__(256) gemm_bn_tc(
        const float* __restrict__ W, const float* __restrict__ bias,
        float* __restrict__ stats) {
    __shared__ __half Ws[DD * SWH];
    __shared__ __half As[64 * SWH];
    __shared__ float ssum[DD], ssq[DD];
    int tid = threadIdx.x;
    if (tid < DD) { ssum[tid] = 0.f; ssq[tid] = 0.f; }
    for (int q = tid; q < DD * DD / 4; q += 256) {
        int k = q >> 4, n4 = (q & 15) * 4;
        float4 w4 = ((const float4*)W)[q];
        Ws[(n4 + 0) * SWH + k] = __float2half_rn(w4.x);
        Ws[(n4 + 1) * SWH + k] = __float2half_rn(w4.y);
        Ws[(n4 + 2) * SWH + k] = __float2half_rn(w4.z);
        Ws[(n4 + 3) * SWH + k] = __float2half_rn(w4.w);
    }
    int lane = tid & 31, warp = tid >> 5;
    int wr = warp & 3, wc = warp >> 2;
    int g = lane >> 2, tig = lane & 3;
#pragma unroll 1
    for (int t2 = 0; t2 < 2; t2++) {
        int tile = blockIdx.x * 2 + t2;
        if (tile >= NTILE) break;
        int node0 = tile * 64;
        __syncthreads();
        for (int q = tid; q < 64 * DD / 8; q += 256) {
            int row = q >> 3, c8 = (q & 7) * 8;
            int n = node0 + row;
            int4 v = (n < NN)
                ? *(const int4*)&g_agg16[(size_t)n * DD + c8]
                : make_int4(0, 0, 0, 0);
            *(int4*)&As[row * SWH + c8] = v;
        }
        __syncthreads();
        float c[4][4] = {};
#pragma unroll
        for (int kk = 0; kk < DD; kk += 16) {
            uint32_t a0 = *(const uint32_t*)&As[(wr * 16 + g) * SWH + kk + 2 * tig];
            uint32_t a1 = *(const uint32_t*)&As[(wr * 16 + g + 8) * SWH + kk + 2 * tig];
            uint32_t a2 = *(const uint32_t*)&As[(wr * 16 + g) * SWH + kk + 2 * tig + 8];
            uint32_t a3 = *(const uint32_t*)&As[(wr * 16 + g + 8) * SWH + kk + 2 * tig + 8];
#pragma unroll
            for (int nt = 0; nt < 4; nt++) {
                int nn = wc * 32 + nt * 8;
                uint32_t b0 = *(const uint32_t*)&Ws[(nn + g) * SWH + kk + 2 * tig];
                uint32_t b1 = *(const uint32_t*)&Ws[(nn + g) * SWH + kk + 2 * tig + 8];
                mma_f16(c[nt][0], c[nt][1], c[nt][2], c[nt][3],
                        a0, a1, a2, a3, b0, b1);
            }
        }
        int r1 = node0 + wr * 16 + g, r2 = r1 + 8;
        bool v1 = (r1 < NN), v2 = (r2 < NN);
#pragma unroll
        for (int nt = 0; nt < 4; nt++) {
            int f = wc * 32 + nt * 8 + tig * 2;
            float b0 = bias[f], b1 = bias[f + 1];
            float s0 = 0.f, s1 = 0.f, q0 = 0.f, q1 = 0.f;
            if (v1) {
                float x = c[nt][0] + b0, y = c[nt][1] + b1;
                *(__half2*)&g_hc16[(size_t)r1 * DD + f] = __floats2half2_rn(x, y);
                s0 += x; s1 += y; q0 += x * x; q1 += y * y;
            }
            if (v2) {
                float x = c[nt][2] + b0, y = c[nt][3] + b1;
                *(__half2*)&g_hc16[(size_t)r2 * DD + f] = __floats2half2_rn(x, y);
                s0 += x; s1 += y; q0 += x * x; q1 += y * y;
            }
#pragma unroll
            for (int off = 4; off <= 16; off <<= 1) {
                s0 += __shfl_xor_sync(0xffffffffu, s0, off);
                s1 += __shfl_xor_sync(0xffffffffu, s1, off);
                q0 += __shfl_xor_sync(0xffffffffu, q0, off);
                q1 += __shfl_xor_sync(0xffffffffu, q1, off);
            }
            if (g == 0) {
                atomicAdd(&ssum[f], s0);     atomicAdd(&ssum[f + 1], s1);
                atomicAdd(&ssq[f], q0);      atomicAdd(&ssq[f + 1], q1);
            }
        }
    }
    __syncthreads();
    if (tid < DD) {
        atomicAdd(&stats[tid],      ssum[tid]);
        atomicAdd(&stats[DD + tid], ssq[tid]);
    }
}

// ---------------------------------------------------------------------------
// BN finalize + apply + leakyrelu + residual; write g_hs16 for next layer.
// 2 chunks per thread for ILP.
__global__ void bn_apply_kernel(const float* __restrict__ gamma,
                                const float* __restrict__ beta,
                                const float* __restrict__ stats) {
    __shared__ float sc[DD], sh[DD];
    int tid = threadIdx.x;
    if (tid < DD) {
        float mean = stats[tid] * (1.f / NN);
        float ex2  = stats[DD + tid] * (1.f / NN);
        float inv  = rsqrtf(ex2 - mean * mean + 1e-5f);
        float s    = gamma[tid] * inv;
        sc[tid] = s;
        sh[tid] = beta[tid] - mean * s;
    }
    __syncthreads();
#pragma unroll
    for (int u = 0; u < 2; u++) {
        int i = blockIdx.x * 512 + u * 256 + tid;   // over NN*16 float4s
        if (i >= NN * (DD / 4)) return;
        int n = i >> 4;
        int f0 = (i & 15) * 4;
        const __half2* cp = (const __half2*)&g_hc16[(size_t)i * 4];
        float2 c01 = __half22float2(cp[0]);
        float2 c23 = __half22float2(cp[1]);
        float4 h4 = ((const float4*)g_h)[i];
        float ns = g_norm_src[n];
        float v;
        v = c01.x * sc[f0 + 0] + sh[f0 + 0]; h4.x += (v >= 0.f) ? v : 0.2f * v;
        v = c01.y * sc[f0 + 1] + sh[f0 + 1]; h4.y += (v >= 0.f) ? v : 0.2f * v;
        v = c23.x * sc[f0 + 2] + sh[f0 + 2]; h4.z += (v >= 0.f) ? v : 0.2f * v;
        v = c23.y * sc[f0 + 3] + sh[f0 + 3]; h4.w += (v >= 0.f) ? v : 0.2f * v;
        ((float4*)g_h)[i] = h4;
        __half2* hp = (__half2*)&g_hs16[(size_t)i * 4];
        hp[0] = __floats2half2_rn(h4.x * ns, h4.y * ns);
        hp[1] = __floats2half2_rn(h4.z * ns, h4.w * ns);
    }
}

// ---------------------------------------------------------------------------
// Final fused kernel: BN(l=3)+leaky+residual, logits + log_softmax.
__global__ void __launch_bounds__(256) out_kernel(
        const float* __restrict__ gamma, const float* __restrict__ beta,
        const float* __restrict__ stats,
        const float* __restrict__ W, const float* __restrict__ b,
        float* __restrict__ out) {
    __shared__ float Ws[DD * NC];   // 10 KB
    __shared__ float bs[NC];
    __shared__ float sc[DD], sh[DD];
    __shared__ float hrow[8][DD];
    int tid = threadIdx.x;          // 256 threads = 8 warps
    for (int i = tid; i < DD * NC; i += 256) Ws[i] = W[i];
    if (tid < NC) bs[tid] = b[tid];
    if (tid < DD) {
        float mean = stats[tid] * (1.f / NN);
        float ex2  = stats[DD + tid] * (1.f / NN);
        float inv  = rsqrtf(ex2 - mean * mean + 1e-5f);
        float s    = gamma[tid] * inv;
        sc[tid] = s;
        sh[tid] = beta[tid] - mean * s;
    }
    __syncthreads();
    int warp = tid >> 5, lane = tid & 31;
    int n = blockIdx.x * 8 + warp;  // NN divisible by 8
    if (n >= NN) return;
    {
        int f = lane * 2;
        float2 c  = __half22float2(*(const __half2*)&g_hc16[(size_t)n * DD + f]);
        float2 h2 = *(const float2*)&g_h[(size_t)n * DD + f];
        float v;
        v = c.x * sc[f]     + sh[f];     h2.x += (v >= 0.f) ? v : 0.2f * v;
        v = c.y * sc[f + 1] + sh[f + 1]; h2.y += (v >= 0.f) ? v : 0.2f * v;
        hrow[warp][f]     = h2.x;
        hrow[warp][f + 1] = h2.y;
    }
    __syncwarp();
    int c0 = lane, c1 = lane + 32;
    bool has1 = (c1 < NC);
    float acc0 = bs[c0];
    float acc1 = has1 ? bs[c1] : 0.f;
#pragma unroll
    for (int k = 0; k < DD; k++) {
        float hv = hrow[warp][k];
        acc0 += hv * Ws[k * NC + c0];
        if (has1) acc1 += hv * Ws[k * NC + c1];
    }
    float m = has1 ? fmaxf(acc0, acc1) : acc0;
#pragma unroll
    for (int off = 16; off; off >>= 1) m = fmaxf(m, __shfl_xor_sync(0xffffffffu, m, off));
    float e = expf(acc0 - m) + (has1 ? expf(acc1 - m) : 0.f);
#pragma unroll
    for (int off = 16; off; off >>= 1) e += __shfl_xor_sync(0xffffffffu, e, off);
    float ls = m + logf(e);
    out[(size_t)n * NC + c0] = acc0 - ls;
    if (has1) out[(size_t)n * NC + c1] = acc1 - ls;
}

// ---------------------------------------------------------------------------
extern "C" void kernel_launch(void* const* d_in, const int* in_sizes, int n_in,
                              void* d_out, int out_size) {
    const float* V     = (const float*)d_in[0];
    const int*   src   = (const int*)d_in[1];
    const int*   dst   = (const int*)d_in[2];
    const float* W_in  = (const float*)d_in[3];
    const float* b_in  = (const float*)d_in[4];
    const float* W_l   = (const float*)d_in[5];
    const float* b_l   = (const float*)d_in[6];
    const float* gamma = (const float*)d_in[7];
    const float* beta  = (const float*)d_in[8];
    const float* W_out = (const float*)d_in[9];
    const float* b_out = (const float*)d_in[10];
    float* out = (float*)d_out;

    float* stats_base;
    cudaGetSymbolAddress((void**)&stats_base, g_stats);

    v_convert_kernel<<<(NN * INV / 8 + 255) / 256, 256>>>(V);
    deg_kernel<<<(NE + 255) / 256, 256>>>(src, dst);
    offsets_kernel<<<NSB, 256>>>();
    fill_kernel<<<(NE + 255) / 256, 256>>>(src, dst);

    input_gemm_tc<<<(NTILE + 1) / 2, 256>>>(W_in, b_in);

    for (int l = 0; l < NLAY; l++) {
        float* stats = stats_base + (size_t)l * 2 * DD;
        gather_kernel<<<NN / 8, 256>>>(stats);
        gemm_bn_tc<<<(NTILE + 1) / 2, 256>>>(W_l + (size_t)l * DD * DD,
                                             b_l + (size_t)l * DD, stats);
        if (l < NLAY - 1) {
            bn_apply_kernel<<<(NN * (DD / 4) + 511) / 512, 256>>>(
                gamma + (size_t)l * DD, beta + (size_t)l * DD, stats);
        }
    }

    out_kernel<<<NN / 8, 256>>>(gamma + (size_t)(NLAY - 1) * DD,
                                beta + (size_t)(NLAY - 1) * DD,
                                stats_base + (size_t)(NLAY - 1) * 2 * DD,
                                W_out, b_out, out);
}

// round 16
// speedup vs baseline: 1.0621x; 1.0508x over previous
#include <cuda_runtime.h>
#include <cuda_fp16.h>
#include <cstdint>

#define NN   100000
#define DD   64
#define INV  128
#define NC   40
#define NE   1600000
#define NLAY 4
#define NSB  391         // offset blocks: ceil(NN/256)
#define SWH  72          // smem stride in halves (144B = 4 banks mod 32)
#define SWI  136         // input gemm stride in halves (272B = 4 banks mod 32)
#define NTILE 1563       // ceil(NN/64)
#define TPB  4           // tiles per block in GEMM kernels

// ---- scratch (device globals: no allocations allowed) ----
__device__ __align__(128) float  g_h[NN * DD];
__device__ __align__(128) __half g_hs16[NN * DD];   // (h * norm_src) in fp16
__device__ __align__(128) __half g_agg16[NN * DD];  // gathered agg in fp16
__device__ __align__(128) __half g_hc16[NN * DD];   // conv output in fp16
__device__ float g_norm_src[NN];
__device__ float g_norm_dst[NN];
__device__ int   g_deg_out[NN];   // out-degree counts (zeroed by offsets)
__device__ int   g_cnt[NN];       // in-degree counts  (zeroed by offsets)
__device__ int   g_row_ptr[NN];
__device__ int   g_row_end[NN];
__device__ int   g_cursor[NN];    // fully overwritten by offsets each call
__device__ int   g_col[NE];
__device__ int   g_total;         // reset by last offsets block
__device__ int   g_done;          // reset by last offsets block
__device__ float g_stats[NLAY * 2 * DD];  // slot l zeroed by gather(l) block 0

// ---------------------------------------------------------------------------
__device__ __forceinline__ void mma_f16(
        float& c0, float& c1, float& c2, float& c3,
        uint32_t a0, uint32_t a1, uint32_t a2, uint32_t a3,
        uint32_t b0, uint32_t b1) {
    asm volatile(
        "mma.sync.aligned.m16n8k16.row.col.f32.f16.f16.f32 "
        "{%0,%1,%2,%3}, {%4,%5,%6,%7}, {%8,%9}, {%0,%1,%2,%3};"
        : "+f"(c0), "+f"(c1), "+f"(c2), "+f"(c3)
        : "r"(a0), "r"(a1), "r"(a2), "r"(a3), "r"(b0), "r"(b1));
}

// ---------------------------------------------------------------------------
__global__ void deg_kernel(const int* __restrict__ src, const int* __restrict__ dst) {
    int i = blockIdx.x * 256 + threadIdx.x;
    if (i < NE) {
        atomicAdd(&g_deg_out[src[i]], 1);
        atomicAdd(&g_cnt[dst[i]], 1);
    }
}

// Single-pass offset allocation: block-local scan + one atomicAdd per block.
// Also restores all prologue counters to zero for the next graph replay.
__global__ void offsets_kernel() {
    __shared__ int s[256];
    __shared__ int base;
    int t = threadIdx.x;
    int i = blockIdx.x * 256 + t;
    int d = 0, dout = 0;
    if (i < NN) {
        d    = g_cnt[i];      g_cnt[i] = 0;        // self-restore for replay
        dout = g_deg_out[i];  g_deg_out[i] = 0;    // self-restore for replay
    }
    s[t] = d;
    __syncthreads();
    for (int off = 1; off < 256; off <<= 1) {
        int v = (t >= off) ? s[t - off] : 0;
        __syncthreads();
        s[t] += v;
        __syncthreads();
    }
    if (t == 255) {
        base = atomicAdd(&g_total, s[255]);
        if (atomicAdd(&g_done, 1) == NSB - 1) {    // last block resets counters
            g_total = 0;
            g_done = 0;
        }
    }
    __syncthreads();
    if (i < NN) {
        int start = base + s[t] - d;
        g_row_ptr[i] = start;
        g_row_end[i] = start + d;
        g_cursor[i]  = start;
        g_norm_dst[i] = rsqrtf(fmaxf((float)d, 1.f));
        g_norm_src[i] = rsqrtf(fmaxf((float)dout, 1.f));
    }
}

__global__ void fill_kernel(const int* __restrict__ src, const int* __restrict__ dst) {
    int i = blockIdx.x * 256 + threadIdx.x;
    if (i < NE) {
        int pos = atomicAdd(&g_cursor[dst[i]], 1);
        g_col[pos] = src[i];
    }
}

// ---------------------------------------------------------------------------
// h = V @ W_in + b_in ; g_hs16 = fp16(h * norm_src).  fp16 m16n8k16 mma.
// Register double-buffered staging: next tile's global loads fly under the
// current tile's MMA. 4 tiles per block (W staged once).
__global__ void __launch_bounds__(256) input_gemm_tc(
        const float* __restrict__ V, const float* __restrict__ W,
        const float* __restrict__ b) {
    __shared__ __half Ws[DD * SWI];    // Wt[n][k] fp16, 17.4 KB
    __shared__ __half As[64 * SWI];    // tile [m][k] fp16, 17.4 KB
    int tid = threadIdx.x;
    // stage W transposed: W[k][n] fp32 -> Wt[n][k] fp16 (once per block)
    for (int q = tid; q < INV * DD / 4; q += 256) {
        int k = q >> 4, n4 = (q & 15) * 4;
        float4 w4 = ((const float4*)W)[q];
        Ws[(n4 + 0) * SWI + k] = __float2half_rn(w4.x);
        Ws[(n4 + 1) * SWI + k] = __float2half_rn(w4.y);
        Ws[(n4 + 2) * SWI + k] = __float2half_rn(w4.z);
        Ws[(n4 + 3) * SWI + k] = __float2half_rn(w4.w);
    }
    int lane = tid & 31, warp = tid >> 5;
    int wr = warp & 3, wc = warp >> 2;
    int g = lane >> 2, tig = lane & 3;
    int tile0 = blockIdx.x * TPB;
    const float4 z4 = make_float4(0.f, 0.f, 0.f, 0.f);
    float4 rbuf[8];
    // preload tile0 into registers (tile0 < NTILE by grid construction)
#pragma unroll
    for (int u = 0; u < 8; u++) {
        int q = u * 256 + tid;
        int row = q >> 5, c4 = (q & 31) * 4;
        int n = tile0 * 64 + row;
        rbuf[u] = (n < NN) ? *(const float4*)&V[(size_t)n * INV + c4] : z4;
    }
#pragma unroll 1
    for (int t = 0; t < TPB; t++) {
        int tile = tile0 + t;
        if (tile >= NTILE) break;
        int node0 = tile * 64;
        __syncthreads();                       // As free; Ws ready (t==0)
        // regs -> smem (with cvt)
#pragma unroll
        for (int u = 0; u < 8; u++) {
            int q = u * 256 + tid;
            int row = q >> 5, c4 = (q & 31) * 4;
            __half2* p = (__half2*)&As[row * SWI + c4];
            p[0] = __floats2half2_rn(rbuf[u].x, rbuf[u].y);
            p[1] = __floats2half2_rn(rbuf[u].z, rbuf[u].w);
        }
        // issue next tile's loads (overlap with compute below)
        if (t + 1 < TPB && tile + 1 < NTILE) {
#pragma unroll
            for (int u = 0; u < 8; u++) {
                int q = u * 256 + tid;
                int row = q >> 5, c4 = (q & 31) * 4;
                int n = (tile + 1) * 64 + row;
                rbuf[u] = (n < NN) ? *(const float4*)&V[(size_t)n * INV + c4] : z4;
            }
        }
        __syncthreads();                       // As ready
        float c[4][4] = {};
#pragma unroll
        for (int kk = 0; kk < INV; kk += 16) {
            uint32_t a0 = *(const uint32_t*)&As[(wr * 16 + g) * SWI + kk + 2 * tig];
            uint32_t a1 = *(const uint32_t*)&As[(wr * 16 + g + 8) * SWI + kk + 2 * tig];
            uint32_t a2 = *(const uint32_t*)&As[(wr * 16 + g) * SWI + kk + 2 * tig + 8];
            uint32_t a3 = *(const uint32_t*)&As[(wr * 16 + g + 8) * SWI + kk + 2 * tig + 8];
#pragma unroll
            for (int nt = 0; nt < 4; nt++) {
                int nn = wc * 32 + nt * 8;
                uint32_t b0 = *(const uint32_t*)&Ws[(nn + g) * SWI + kk + 2 * tig];
                uint32_t b1 = *(const uint32_t*)&Ws[(nn + g) * SWI + kk + 2 * tig + 8];
                mma_f16(c[nt][0], c[nt][1], c[nt][2], c[nt][3],
                        a0, a1, a2, a3, b0, b1);
            }
        }
        int r1 = node0 + wr * 16 + g, r2 = r1 + 8;
        bool v1 = (r1 < NN), v2 = (r2 < NN);
        float ns1 = v1 ? g_norm_src[r1] : 0.f;
        float ns2 = v2 ? g_norm_src[r2] : 0.f;
#pragma unroll
        for (int nt = 0; nt < 4; nt++) {
            int f = wc * 32 + nt * 8 + tig * 2;
            float b0 = b[f], b1 = b[f + 1];
            if (v1) {
                float x = c[nt][0] + b0, y = c[nt][1] + b1;
                *(float2*)&g_h[(size_t)r1 * DD + f] = make_float2(x, y);
                *(__half2*)&g_hs16[(size_t)r1 * DD + f] = __floats2half2_rn(x * ns1, y * ns1);
            }
            if (v2) {
                float x = c[nt][2] + b0, y = c[nt][3] + b1;
                *(float2*)&g_h[(size_t)r2 * DD + f] = make_float2(x, y);
                *(__half2*)&g_hs16[(size_t)r2 * DD + f] = __floats2half2_rn(x * ns2, y * ns2);
            }
        }
    }
}

// ---------------------------------------------------------------------------
// CSR gather segment-sum, fp16 rows, LDG.128, masked MLP-4 (near BW floor).
// Block 0 also zeroes this layer's BN stats slot (gemm runs strictly after).
#define ACC4(r) do { const __half2* _hh = (const __half2*)&(r); float2 _t;   \
    _t = __half22float2(_hh[0]); ac0.x += _t.x; ac0.y += _t.y;               \
    _t = __half22float2(_hh[1]); ac1.x += _t.x; ac1.y += _t.y;               \
    _t = __half22float2(_hh[2]); ac2.x += _t.x; ac2.y += _t.y;               \
    _t = __half22float2(_hh[3]); ac3.x += _t.x; ac3.y += _t.y; } while (0)

__global__ void __launch_bounds__(256) gather_kernel(float* __restrict__ stats) {
    int tid = threadIdx.x;
    if (blockIdx.x == 0 && tid < 2 * DD) stats[tid] = 0.f;
    int lane = tid & 31;
    int node = blockIdx.x * 8 + (tid >> 5);       // NN divisible by 8
    int group = lane >> 3;                         // 0..3
    int sub   = lane & 7;                          // 0..7
    int e0  = __ldg(&g_row_ptr[node]);
    int end = __ldg(&g_row_end[node]);
    const float4* __restrict__ hs = (const float4*)g_hs16;
    const float4 z4 = make_float4(0.f, 0.f, 0.f, 0.f);

    float2 ac0 = {0.f, 0.f}, ac1 = {0.f, 0.f}, ac2 = {0.f, 0.f}, ac3 = {0.f, 0.f};
    for (int e = e0 + group; e < end; e += 16) {
        int i1 = e + 4, i2 = e + 8, i3 = e + 12;
        int s0 = __ldg(&g_col[e]);
        int s1 = __ldg(&g_col[i1 < end ? i1 : e]);
        int s2 = __ldg(&g_col[i2 < end ? i2 : e]);
        int s3 = __ldg(&g_col[i3 < end ? i3 : e]);
        float4 r0 = hs[(size_t)s0 * 8 + sub];
        float4 r1 = hs[(size_t)s1 * 8 + sub];
        float4 r2 = hs[(size_t)s2 * 8 + sub];
        float4 r3 = hs[(size_t)s3 * 8 + sub];
        if (i1 >= end) r1 = z4;
        if (i2 >= end) r2 = z4;
        if (i3 >= end) r3 = z4;
        ACC4(r0); ACC4(r1); ACC4(r2); ACC4(r3);
    }
#pragma unroll
    for (int off = 8; off <= 16; off <<= 1) {
        ac0.x += __shfl_xor_sync(0xffffffffu, ac0.x, off);
        ac0.y += __shfl_xor_sync(0xffffffffu, ac0.y, off);
        ac1.x += __shfl_xor_sync(0xffffffffu, ac1.x, off);
        ac1.y += __shfl_xor_sync(0xffffffffu, ac1.y, off);
        ac2.x += __shfl_xor_sync(0xffffffffu, ac2.x, off);
        ac2.y += __shfl_xor_sync(0xffffffffu, ac2.y, off);
        ac3.x += __shfl_xor_sync(0xffffffffu, ac3.x, off);
        ac3.y += __shfl_xor_sync(0xffffffffu, ac3.y, off);
    }
    float nd = g_norm_dst[node];
    if (lane < 16) {
        int half = lane >> 3;
        __half2 o0, o1;
        if (half == 0) {
            o0 = __floats2half2_rn(ac0.x * nd, ac0.y * nd);
            o1 = __floats2half2_rn(ac1.x * nd, ac1.y * nd);
        } else {
            o0 = __floats2half2_rn(ac2.x * nd, ac2.y * nd);
            o1 = __floats2half2_rn(ac3.x * nd, ac3.y * nd);
        }
        __half2* op = (__half2*)&g_agg16[(size_t)node * DD + sub * 8 + half * 4];
        op[0] = o0; op[1] = o1;
    }
}

// ---------------------------------------------------------------------------
// hc16 = fp16(agg @ W + b) via fp16 mma; BN stats into stats slot.
// Register double-buffered A staging; 4 tiles per block (W staged once).
__global__ void __launch_bounds__(256) gemm_bn_tc(
        const float* __restrict__ W, const float* __restrict__ bias,
        float* __restrict__ stats) {
    __shared__ __half Ws[DD * SWH];
    __shared__ __half As[64 * SWH];
    __shared__ float ssum[DD], ssq[DD];
    int tid = threadIdx.x;
    if (tid < DD) { ssum[tid] = 0.f; ssq[tid] = 0.f; }
    for (int q = tid; q < DD * DD / 4; q += 256) {
        int k = q >> 4, n4 = (q & 15) * 4;
        float4 w4 = ((const float4*)W)[q];
        Ws[(n4 + 0) * SWH + k] = __float2half_rn(w4.x);
        Ws[(n4 + 1) * SWH + k] = __float2half_rn(w4.y);
        Ws[(n4 + 2) * SWH + k] = __float2half_rn(w4.z);
        Ws[(n4 + 3) * SWH + k] = __float2half_rn(w4.w);
    }
    int lane = tid & 31, warp = tid >> 5;
    int wr = warp & 3, wc = warp >> 2;
    int g = lane >> 2, tig = lane & 3;
    int tile0 = blockIdx.x * TPB;
    const int4 zi = make_int4(0, 0, 0, 0);
    int4 rbuf[2];
    // preload tile0 (64 rows x 64 halves = 512 int4 / 256 thr = 2 each)
#pragma unroll
    for (int u = 0; u < 2; u++) {
        int q = u * 256 + tid;
        int row = q >> 3, c8 = (q & 7) * 8;
        int n = tile0 * 64 + row;
        rbuf[u] = (n < NN) ? *(const int4*)&g_agg16[(size_t)n * DD + c8] : zi;
    }
#pragma unroll 1
    for (int t = 0; t < TPB; t++) {
        int tile = tile0 + t;
        if (tile >= NTILE) break;
        int node0 = tile * 64;
        __syncthreads();
#pragma unroll
        for (int u = 0; u < 2; u++) {
            int q = u * 256 + tid;
            int row = q >> 3, c8 = (q & 7) * 8;
            *(int4*)&As[row * SWH + c8] = rbuf[u];
        }
        if (t + 1 < TPB && tile + 1 < NTILE) {
#pragma unroll
            for (int u = 0; u < 2; u++) {
                int q = u * 256 + tid;
                int row = q >> 3, c8 = (q & 7) * 8;
                int n = (tile + 1) * 64 + row;
                rbuf[u] = (n < NN) ? *(const int4*)&g_agg16[(size_t)n * DD + c8] : zi;
            }
        }
        __syncthreads();
        float c[4][4] = {};
#pragma unroll
        for (int kk = 0; kk < DD; kk += 16) {
            uint32_t a0 = *(const uint32_t*)&As[(wr * 16 + g) * SWH + kk + 2 * tig];
            uint32_t a1 = *(const uint32_t*)&As[(wr * 16 + g + 8) * SWH + kk + 2 * tig];
            uint32_t a2 = *(const uint32_t*)&As[(wr * 16 + g) * SWH + kk + 2 * tig + 8];
            uint32_t a3 = *(const uint32_t*)&As[(wr * 16 + g + 8) * SWH + kk + 2 * tig + 8];
#pragma unroll
            for (int nt = 0; nt < 4; nt++) {
                int nn = wc * 32 + nt * 8;
                uint32_t b0 = *(const uint32_t*)&Ws[(nn + g) * SWH + kk + 2 * tig];
                uint32_t b1 = *(const uint32_t*)&Ws[(nn + g) * SWH + kk + 2 * tig + 8];
                mma_f16(c[nt][0], c[nt][1], c[nt][2], c[nt][3],
                        a0, a1, a2, a3, b0, b1);
            }
        }
        int r1 = node0 + wr * 16 + g, r2 = r1 + 8;
        bool v1 = (r1 < NN), v2 = (r2 < NN);
#pragma unroll
        for (int nt = 0; nt < 4; nt++) {
            int f = wc * 32 + nt * 8 + tig * 2;
            float b0 = bias[f], b1 = bias[f + 1];
            float s0 = 0.f, s1 = 0.f, q0 = 0.f, q1 = 0.f;
            if (v1) {
                float x = c[nt][0] + b0, y = c[nt][1] + b1;
                *(__half2*)&g_hc16[(size_t)r1 * DD + f] = __floats2half2_rn(x, y);
                s0 += x; s1 += y; q0 += x * x; q1 += y * y;
            }
            if (v2) {
                float x = c[nt][2] + b0, y = c[nt][3] + b1;
                *(__half2*)&g_hc16[(size_t)r2 * DD + f] = __floats2half2_rn(x, y);
                s0 += x; s1 += y; q0 += x * x; q1 += y * y;
            }
#pragma unroll
            for (int off = 4; off <= 16; off <<= 1) {
                s0 += __shfl_xor_sync(0xffffffffu, s0, off);
                s1 += __shfl_xor_sync(0xffffffffu, s1, off);
                q0 += __shfl_xor_sync(0xffffffffu, q0, off);
                q1 += __shfl_xor_sync(0xffffffffu, q1, off);
            }
            if (g == 0) {
                atomicAdd(&ssum[f], s0);     atomicAdd(&ssum[f + 1], s1);
                atomicAdd(&ssq[f], q0);      atomicAdd(&ssq[f + 1], q1);
            }
        }
    }
    __syncthreads();
    if (tid < DD) {
        atomicAdd(&stats[tid],      ssum[tid]);
        atomicAdd(&stats[DD + tid], ssq[tid]);
    }
}

// ---------------------------------------------------------------------------
// BN finalize + apply + leakyrelu + residual; write g_hs16 for next layer.
// 2 chunks per thread for ILP.
__global__ void bn_apply_kernel(const float* __restrict__ gamma,
                                const float* __restrict__ beta,
                                const float* __restrict__ stats) {
    __shared__ float sc[DD], sh[DD];
    int tid = threadIdx.x;
    if (tid < DD) {
        float mean = stats[tid] * (1.f / NN);
        float ex2  = stats[DD + tid] * (1.f / NN);
        float inv  = rsqrtf(ex2 - mean * mean + 1e-5f);
        float s    = gamma[tid] * inv;
        sc[tid] = s;
        sh[tid] = beta[tid] - mean * s;
    }
    __syncthreads();
#pragma unroll
    for (int u = 0; u < 2; u++) {
        int i = blockIdx.x * 512 + u * 256 + tid;   // over NN*16 float4s
        if (i >= NN * (DD / 4)) return;
        int n = i >> 4;
        int f0 = (i & 15) * 4;
        const __half2* cp = (const __half2*)&g_hc16[(size_t)i * 4];
        float2 c01 = __half22float2(cp[0]);
        float2 c23 = __half22float2(cp[1]);
        float4 h4 = ((const float4*)g_h)[i];
        float ns = g_norm_src[n];
        float v;
        v = c01.x * sc[f0 + 0] + sh[f0 + 0]; h4.x += (v >= 0.f) ? v : 0.2f * v;
        v = c01.y * sc[f0 + 1] + sh[f0 + 1]; h4.y += (v >= 0.f) ? v : 0.2f * v;
        v = c23.x * sc[f0 + 2] + sh[f0 + 2]; h4.z += (v >= 0.f) ? v : 0.2f * v;
        v = c23.y * sc[f0 + 3] + sh[f0 + 3]; h4.w += (v >= 0.f) ? v : 0.2f * v;
        ((float4*)g_h)[i] = h4;
        __half2* hp = (__half2*)&g_hs16[(size_t)i * 4];
        hp[0] = __floats2half2_rn(h4.x * ns, h4.y * ns);
        hp[1] = __floats2half2_rn(h4.z * ns, h4.w * ns);
    }
}

// ---------------------------------------------------------------------------
// Final fused kernel: BN(l=3)+leaky+residual, logits + log_softmax.
__global__ void __launch_bounds__(256) out_kernel(
        const float* __restrict__ gamma, const float* __restrict__ beta,
        const float* __restrict__ stats,
        const float* __restrict__ W, const float* __restrict__ b,
        float* __restrict__ out) {
    __shared__ float Ws[DD * NC];   // 10 KB
    __shared__ float bs[NC];
    __shared__ float sc[DD], sh[DD];
    __shared__ float hrow[8][DD];
    int tid = threadIdx.x;          // 256 threads = 8 warps
    for (int i = tid; i < DD * NC; i += 256) Ws[i] = W[i];
    if (tid < NC) bs[tid] = b[tid];
    if (tid < DD) {
        float mean = stats[tid] * (1.f / NN);
        float ex2  = stats[DD + tid] * (1.f / NN);
        float inv  = rsqrtf(ex2 - mean * mean + 1e-5f);
        float s    = gamma[tid] * inv;
        sc[tid] = s;
        sh[tid] = beta[tid] - mean * s;
    }
    __syncthreads();
    int warp = tid >> 5, lane = tid & 31;
    int n = blockIdx.x * 8 + warp;  // NN divisible by 8
    if (n >= NN) return;
    {
        int f = lane * 2;
        float2 c  = __half22float2(*(const __half2*)&g_hc16[(size_t)n * DD + f]);
        float2 h2 = *(const float2*)&g_h[(size_t)n * DD + f];
        float v;
        v = c.x * sc[f]     + sh[f];     h2.x += (v >= 0.f) ? v : 0.2f * v;
        v = c.y * sc[f + 1] + sh[f + 1]; h2.y += (v >= 0.f) ? v : 0.2f * v;
        hrow[warp][f]     = h2.x;
        hrow[warp][f + 1] = h2.y;
    }
    __syncwarp();
    int c0 = lane, c1 = lane + 32;
    bool has1 = (c1 < NC);
    float acc0 = bs[c0];
    float acc1 = has1 ? bs[c1] : 0.f;
#pragma unroll
    for (int k = 0; k < DD; k++) {
        float hv = hrow[warp][k];
        acc0 += hv * Ws[k * NC + c0];
        if (has1) acc1 += hv * Ws[k * NC + c1];
    }
    float m = has1 ? fmaxf(acc0, acc1) : acc0;
#pragma unroll
    for (int off = 16; off; off >>= 1) m = fmaxf(m, __shfl_xor_sync(0xffffffffu, m, off));
    float e = expf(acc0 - m) + (has1 ? expf(acc1 - m) : 0.f);
#pragma unroll
    for (int off = 16; off; off >>= 1) e += __shfl_xor_sync(0xffffffffu, e, off);
    float ls = m + logf(e);
    out[(size_t)n * NC + c0] = acc0 - ls;
    if (has1) out[(size_t)n * NC + c1] = acc1 - ls;
}

// ---------------------------------------------------------------------------
extern "C" void kernel_launch(void* const* d_in, const int* in_sizes, int n_in,
                              void* d_out, int out_size) {
    const float* V     = (const float*)d_in[0];
    const int*   src   = (const int*)d_in[1];
    const int*   dst   = (const int*)d_in[2];
    const float* W_in  = (const float*)d_in[3];
    const float* b_in  = (const float*)d_in[4];
    const float* W_l   = (const float*)d_in[5];
    const float* b_l   = (const float*)d_in[6];
    const float* gamma = (const float*)d_in[7];
    const float* beta  = (const float*)d_in[8];
    const float* W_out = (const float*)d_in[9];
    const float* b_out = (const float*)d_in[10];
    float* out = (float*)d_out;

    float* stats_base;
    cudaGetSymbolAddress((void**)&stats_base, g_stats);

    deg_kernel<<<(NE + 255) / 256, 256>>>(src, dst);
    offsets_kernel<<<NSB, 256>>>();
    fill_kernel<<<(NE + 255) / 256, 256>>>(src, dst);

    input_gemm_tc<<<(NTILE + TPB - 1) / TPB, 256>>>(V, W_in, b_in);

    for (int l = 0; l < NLAY; l++) {
        float* stats = stats_base + (size_t)l * 2 * DD;
        gather_kernel<<<NN / 8, 256>>>(stats);
        gemm_bn_tc<<<(NTILE + TPB - 1) / TPB, 256>>>(W_l + (size_t)l * DD * DD,
                                                     b_l + (size_t)l * DD, stats);
        if (l < NLAY - 1) {
            bn_apply_kernel<<<(NN * (DD / 4) + 511) / 512, 256>>>(
                gamma + (size_t)l * DD, beta + (size_t)l * DD, stats);
        }
    }

    out_kernel<<<NN / 8, 256>>>(gamma + (size_t)(NLAY - 1) * DD,
                                beta + (size_t)(NLAY - 1) * DD,
                                stats_base + (size_t)(NLAY - 1) * 2 * DD,
                                W_out, b_out, out);
}

// round 17
// speedup vs baseline: 1.0780x; 1.0150x over previous
#include <cuda_runtime.h>
#include <cuda_fp16.h>
#include <cstdint>

#define NN   100000
#define DD   64
#define INV  128
#define NC   40
#define NE   1600000
#define NLAY 4
#define NSB  391         // offset blocks: ceil(NN/256)
#define SWH  72          // smem stride in halves (144B = 4 banks mod 32)
#define SWI  136         // input gemm stride in halves (272B = 4 banks mod 32)
#define NTILE 1563       // ceil(NN/64)
#define TPB  4           // tiles per block in GEMM kernels

// PDL: cascade dependent launches; wait before first graph-data read.
#define PDL_TRIGGER() asm volatile("griddepcontrol.launch_dependents;" ::: "memory")
#define PDL_WAIT()    asm volatile("griddepcontrol.wait;" ::: "memory")

// ---- scratch (device globals: no allocations allowed) ----
__device__ __align__(128) float  g_h[NN * DD];
__device__ __align__(128) __half g_hs16[NN * DD];   // (h * norm_src) in fp16
__device__ __align__(128) __half g_agg16[NN * DD];  // gathered agg in fp16
__device__ __align__(128) __half g_hc16[NN * DD];   // conv output in fp16
__device__ float g_norm_src[NN];
__device__ float g_norm_dst[NN];
__device__ int   g_deg_out[NN];   // out-degree counts (zeroed by offsets)
__device__ int   g_cnt[NN];       // in-degree counts  (zeroed by offsets)
__device__ int   g_row_ptr[NN];
__device__ int   g_row_end[NN];
__device__ int   g_cursor[NN];    // fully overwritten by offsets each call
__device__ int   g_col[NE];
__device__ int   g_total;         // reset by last offsets block
__device__ int   g_done;          // reset by last offsets block
__device__ float g_stats[NLAY * 2 * DD];  // slot l zeroed by gather(l) block 0

// ---------------------------------------------------------------------------
__device__ __forceinline__ void mma_f16(
        float& c0, float& c1, float& c2, float& c3,
        uint32_t a0, uint32_t a1, uint32_t a2, uint32_t a3,
        uint32_t b0, uint32_t b1) {
    asm volatile(
        "mma.sync.aligned.m16n8k16.row.col.f32.f16.f16.f32 "
        "{%0,%1,%2,%3}, {%4,%5,%6,%7}, {%8,%9}, {%0,%1,%2,%3};"
        : "+f"(c0), "+f"(c1), "+f"(c2), "+f"(c3)
        : "r"(a0), "r"(a1), "r"(a2), "r"(a3), "r"(b0), "r"(b1));
}

// ---------------------------------------------------------------------------
__global__ void deg_kernel(const int* __restrict__ src, const int* __restrict__ dst) {
    PDL_TRIGGER();
    int i = blockIdx.x * 256 + threadIdx.x;
    if (i < NE) {
        atomicAdd(&g_deg_out[src[i]], 1);
        atomicAdd(&g_cnt[dst[i]], 1);
    }
}

// Single-pass offset allocation: block-local scan + one atomicAdd per block.
// Also restores all prologue counters to zero for the next graph replay.
__global__ void offsets_kernel() {
    PDL_TRIGGER();
    __shared__ int s[256];
    __shared__ int base;
    int t = threadIdx.x;
    int i = blockIdx.x * 256 + t;
    PDL_WAIT();                               // need deg counts
    int d = 0, dout = 0;
    if (i < NN) {
        d    = g_cnt[i];      g_cnt[i] = 0;        // self-restore for replay
        dout = g_deg_out[i];  g_deg_out[i] = 0;    // self-restore for replay
    }
    s[t] = d;
    __syncthreads();
    for (int off = 1; off < 256; off <<= 1) {
        int v = (t >= off) ? s[t - off] : 0;
        __syncthreads();
        s[t] += v;
        __syncthreads();
    }
    if (t == 255) {
        base = atomicAdd(&g_total, s[255]);
        if (atomicAdd(&g_done, 1) == NSB - 1) {    // last block resets counters
            g_total = 0;
            g_done = 0;
        }
    }
    __syncthreads();
    if (i < NN) {
        int start = base + s[t] - d;
        g_row_ptr[i] = start;
        g_row_end[i] = start + d;
        g_cursor[i]  = start;
        g_norm_dst[i] = rsqrtf(fmaxf((float)d, 1.f));
        g_norm_src[i] = rsqrtf(fmaxf((float)dout, 1.f));
    }
}

__global__ void fill_kernel(const int* __restrict__ src, const int* __restrict__ dst) {
    PDL_TRIGGER();
    int i = blockIdx.x * 256 + threadIdx.x;
    int s = 0, d = 0;
    if (i < NE) { s = src[i]; d = dst[i]; }   // pure-input prologue
    PDL_WAIT();                               // need g_cursor from offsets
    if (i < NE) {
        int pos = atomicAdd(&g_cursor[d], 1);
        g_col[pos] = s;
    }
}

// ---------------------------------------------------------------------------
// h = V @ W_in + b_in ; g_hs16 = fp16(h * norm_src).  fp16 m16n8k16 mma.
// Register double-buffered staging; 4 tiles per block.  Pre-wait prologue:
// W staging + tile0 preload (inputs only).
__global__ void __launch_bounds__(256) input_gemm_tc(
        const float* __restrict__ V, const float* __restrict__ W,
        const float* __restrict__ b) {
    PDL_TRIGGER();
    __shared__ __half Ws[DD * SWI];    // Wt[n][k] fp16, 17.4 KB
    __shared__ __half As[64 * SWI];    // tile [m][k] fp16, 17.4 KB
    int tid = threadIdx.x;
    for (int q = tid; q < INV * DD / 4; q += 256) {
        int k = q >> 4, n4 = (q & 15) * 4;
        float4 w4 = ((const float4*)W)[q];
        Ws[(n4 + 0) * SWI + k] = __float2half_rn(w4.x);
        Ws[(n4 + 1) * SWI + k] = __float2half_rn(w4.y);
        Ws[(n4 + 2) * SWI + k] = __float2half_rn(w4.z);
        Ws[(n4 + 3) * SWI + k] = __float2half_rn(w4.w);
    }
    int lane = tid & 31, warp = tid >> 5;
    int wr = warp & 3, wc = warp >> 2;
    int g = lane >> 2, tig = lane & 3;
    int tile0 = blockIdx.x * TPB;
    const float4 z4 = make_float4(0.f, 0.f, 0.f, 0.f);
    float4 rbuf[8];
#pragma unroll
    for (int u = 0; u < 8; u++) {
        int q = u * 256 + tid;
        int row = q >> 5, c4 = (q & 31) * 4;
        int n = tile0 * 64 + row;
        rbuf[u] = (n < NN) ? *(const float4*)&V[(size_t)n * INV + c4] : z4;
    }
    PDL_WAIT();                               // need g_norm_src (epilogue)
#pragma unroll 1
    for (int t = 0; t < TPB; t++) {
        int tile = tile0 + t;
        if (tile >= NTILE) break;
        int node0 = tile * 64;
        __syncthreads();
#pragma unroll
        for (int u = 0; u < 8; u++) {
            int q = u * 256 + tid;
            int row = q >> 5, c4 = (q & 31) * 4;
            __half2* p = (__half2*)&As[row * SWI + c4];
            p[0] = __floats2half2_rn(rbuf[u].x, rbuf[u].y);
            p[1] = __floats2half2_rn(rbuf[u].z, rbuf[u].w);
        }
        if (t + 1 < TPB && tile + 1 < NTILE) {
#pragma unroll
            for (int u = 0; u < 8; u++) {
                int q = u * 256 + tid;
                int row = q >> 5, c4 = (q & 31) * 4;
                int n = (tile + 1) * 64 + row;
                rbuf[u] = (n < NN) ? *(const float4*)&V[(size_t)n * INV + c4] : z4;
            }
        }
        __syncthreads();
        float c[4][4] = {};
#pragma unroll
        for (int kk = 0; kk < INV; kk += 16) {
            uint32_t a0 = *(const uint32_t*)&As[(wr * 16 + g) * SWI + kk + 2 * tig];
            uint32_t a1 = *(const uint32_t*)&As[(wr * 16 + g + 8) * SWI + kk + 2 * tig];
            uint32_t a2 = *(const uint32_t*)&As[(wr * 16 + g) * SWI + kk + 2 * tig + 8];
            uint32_t a3 = *(const uint32_t*)&As[(wr * 16 + g + 8) * SWI + kk + 2 * tig + 8];
#pragma unroll
            for (int nt = 0; nt < 4; nt++) {
                int nn = wc * 32 + nt * 8;
                uint32_t b0 = *(const uint32_t*)&Ws[(nn + g) * SWI + kk + 2 * tig];
                uint32_t b1 = *(const uint32_t*)&Ws[(nn + g) * SWI + kk + 2 * tig + 8];
                mma_f16(c[nt][0], c[nt][1], c[nt][2], c[nt][3],
                        a0, a1, a2, a3, b0, b1);
            }
        }
        int r1 = node0 + wr * 16 + g, r2 = r1 + 8;
        bool v1 = (r1 < NN), v2 = (r2 < NN);
        float ns1 = v1 ? g_norm_src[r1] : 0.f;
        float ns2 = v2 ? g_norm_src[r2] : 0.f;
#pragma unroll
        for (int nt = 0; nt < 4; nt++) {
            int f = wc * 32 + nt * 8 + tig * 2;
            float b0 = b[f], b1 = b[f + 1];
            if (v1) {
                float x = c[nt][0] + b0, y = c[nt][1] + b1;
                *(float2*)&g_h[(size_t)r1 * DD + f] = make_float2(x, y);
                *(__half2*)&g_hs16[(size_t)r1 * DD + f] = __floats2half2_rn(x * ns1, y * ns1);
            }
            if (v2) {
                float x = c[nt][2] + b0, y = c[nt][3] + b1;
                *(float2*)&g_h[(size_t)r2 * DD + f] = make_float2(x, y);
                *(__half2*)&g_hs16[(size_t)r2 * DD + f] = __floats2half2_rn(x * ns2, y * ns2);
            }
        }
    }
}

// ---------------------------------------------------------------------------
// CSR gather segment-sum, fp16 rows, LDG.128, masked MLP-4 (near BW floor).
// Block 0 zeroes this layer's BN stats slot (untouched earlier this replay).
#define ACC4(r) do { const __half2* _hh = (const __half2*)&(r); float2 _t;   \
    _t = __half22float2(_hh[0]); ac0.x += _t.x; ac0.y += _t.y;               \
    _t = __half22float2(_hh[1]); ac1.x += _t.x; ac1.y += _t.y;               \
    _t = __half22float2(_hh[2]); ac2.x += _t.x; ac2.y += _t.y;               \
    _t = __half22float2(_hh[3]); ac3.x += _t.x; ac3.y += _t.y; } while (0)

__global__ void __launch_bounds__(256) gather_kernel(float* __restrict__ stats) {
    PDL_TRIGGER();
    int tid = threadIdx.x;
    if (blockIdx.x == 0 && tid < 2 * DD) stats[tid] = 0.f;
    int lane = tid & 31;
    int node = blockIdx.x * 8 + (tid >> 5);       // NN divisible by 8
    int group = lane >> 3;                         // 0..3
    int sub   = lane & 7;                          // 0..7
    PDL_WAIT();                               // need hs16 (+ CSR via transitivity)
    int e0  = __ldg(&g_row_ptr[node]);
    int end = __ldg(&g_row_end[node]);
    const float4* __restrict__ hs = (const float4*)g_hs16;
    const float4 z4 = make_float4(0.f, 0.f, 0.f, 0.f);

    float2 ac0 = {0.f, 0.f}, ac1 = {0.f, 0.f}, ac2 = {0.f, 0.f}, ac3 = {0.f, 0.f};
    for (int e = e0 + group; e < end; e += 16) {
        int i1 = e + 4, i2 = e + 8, i3 = e + 12;
        int s0 = __ldg(&g_col[e]);
        int s1 = __ldg(&g_col[i1 < end ? i1 : e]);
        int s2 = __ldg(&g_col[i2 < end ? i2 : e]);
        int s3 = __ldg(&g_col[i3 < end ? i3 : e]);
        float4 r0 = hs[(size_t)s0 * 8 + sub];
        float4 r1 = hs[(size_t)s1 * 8 + sub];
        float4 r2 = hs[(size_t)s2 * 8 + sub];
        float4 r3 = hs[(size_t)s3 * 8 + sub];
        if (i1 >= end) r1 = z4;
        if (i2 >= end) r2 = z4;
        if (i3 >= end) r3 = z4;
        ACC4(r0); ACC4(r1); ACC4(r2); ACC4(r3);
    }
#pragma unroll
    for (int off = 8; off <= 16; off <<= 1) {
        ac0.x += __shfl_xor_sync(0xffffffffu, ac0.x, off);
        ac0.y += __shfl_xor_sync(0xffffffffu, ac0.y, off);
        ac1.x += __shfl_xor_sync(0xffffffffu, ac1.x, off);
        ac1.y += __shfl_xor_sync(0xffffffffu, ac1.y, off);
        ac2.x += __shfl_xor_sync(0xffffffffu, ac2.x, off);
        ac2.y += __shfl_xor_sync(0xffffffffu, ac2.y, off);
        ac3.x += __shfl_xor_sync(0xffffffffu, ac3.x, off);
        ac3.y += __shfl_xor_sync(0xffffffffu, ac3.y, off);
    }
    float nd = g_norm_dst[node];
    if (lane < 16) {
        int half = lane >> 3;
        __half2 o0, o1;
        if (half == 0) {
            o0 = __floats2half2_rn(ac0.x * nd, ac0.y * nd);
            o1 = __floats2half2_rn(ac1.x * nd, ac1.y * nd);
        } else {
            o0 = __floats2half2_rn(ac2.x * nd, ac2.y * nd);
            o1 = __floats2half2_rn(ac3.x * nd, ac3.y * nd);
        }
        __half2* op = (__half2*)&g_agg16[(size_t)node * DD + sub * 8 + half * 4];
        op[0] = o0; op[1] = o1;
    }
}

// ---------------------------------------------------------------------------
// hc16 = fp16(agg @ W + b) via fp16 mma; BN stats into stats slot.
// Register double-buffered A staging; 4 tiles per block.  W staged pre-wait.
__global__ void __launch_bounds__(256) gemm_bn_tc(
        const float* __restrict__ W, const float* __restrict__ bias,
        float* __restrict__ stats) {
    PDL_TRIGGER();
    __shared__ __half Ws[DD * SWH];
    __shared__ __half As[64 * SWH];
    __shared__ float ssum[DD], ssq[DD];
    int tid = threadIdx.x;
    if (tid < DD) { ssum[tid] = 0.f; ssq[tid] = 0.f; }
    for (int q = tid; q < DD * DD / 4; q += 256) {
        int k = q >> 4, n4 = (q & 15) * 4;
        float4 w4 = ((const float4*)W)[q];
        Ws[(n4 + 0) * SWH + k] = __float2half_rn(w4.x);
        Ws[(n4 + 1) * SWH + k] = __float2half_rn(w4.y);
        Ws[(n4 + 2) * SWH + k] = __float2half_rn(w4.z);
        Ws[(n4 + 3) * SWH + k] = __float2half_rn(w4.w);
    }
    int lane = tid & 31, warp = tid >> 5;
    int wr = warp & 3, wc = warp >> 2;
    int g = lane >> 2, tig = lane & 3;
    int tile0 = blockIdx.x * TPB;
    const int4 zi = make_int4(0, 0, 0, 0);
    int4 rbuf[2];
    PDL_WAIT();                               // need agg16 from gather
#pragma unroll
    for (int u = 0; u < 2; u++) {
        int q = u * 256 + tid;
        int row = q >> 3, c8 = (q & 7) * 8;
        int n = tile0 * 64 + row;
        rbuf[u] = (n < NN) ? *(const int4*)&g_agg16[(size_t)n * DD + c8] : zi;
    }
#pragma unroll 1
    for (int t = 0; t < TPB; t++) {
        int tile = tile0 + t;
        if (tile >= NTILE) break;
        int node0 = tile * 64;
        __syncthreads();
#pragma unroll
        for (int u = 0; u < 2; u++) {
            int q = u * 256 + tid;
            int row = q >> 3, c8 = (q & 7) * 8;
            *(int4*)&As[row * SWH + c8] = rbuf[u];
        }
        if (t + 1 < TPB && tile + 1 < NTILE) {
#pragma unroll
            for (int u = 0; u < 2; u++) {
                int q = u * 256 + tid;
                int row = q >> 3, c8 = (q & 7) * 8;
                int n = (tile + 1) * 64 + row;
                rbuf[u] = (n < NN) ? *(const int4*)&g_agg16[(size_t)n * DD + c8] : zi;
            }
        }
        __syncthreads();
        float c[4][4] = {};
#pragma unroll
        for (int kk = 0; kk < DD; kk += 16) {
            uint32_t a0 = *(const uint32_t*)&As[(wr * 16 + g) * SWH + kk + 2 * tig];
            uint32_t a1 = *(const uint32_t*)&As[(wr * 16 + g + 8) * SWH + kk + 2 * tig];
            uint32_t a2 = *(const uint32_t*)&As[(wr * 16 + g) * SWH + kk + 2 * tig + 8];
            uint32_t a3 = *(const uint32_t*)&As[(wr * 16 + g + 8) * SWH + kk + 2 * tig + 8];
#pragma unroll
            for (int nt = 0; nt < 4; nt++) {
                int nn = wc * 32 + nt * 8;
                uint32_t b0 = *(const uint32_t*)&Ws[(nn + g) * SWH + kk + 2 * tig];
                uint32_t b1 = *(const uint32_t*)&Ws[(nn + g) * SWH + kk + 2 * tig + 8];
                mma_f16(c[nt][0], c[nt][1], c[nt][2], c[nt][3],
                        a0, a1, a2, a3, b0, b1);
            }
        }
        int r1 = node0 + wr * 16 + g, r2 = r1 + 8;
        bool v1 = (r1 < NN), v2 = (r2 < NN);
#pragma unroll
        for (int nt = 0; nt < 4; nt++) {
            int f = wc * 32 + nt * 8 + tig * 2;
            float b0 = bias[f], b1 = bias[f + 1];
            float s0 = 0.f, s1 = 0.f, q0 = 0.f, q1 = 0.f;
            if (v1) {
                float x = c[nt][0] + b0, y = c[nt][1] + b1;
                *(__half2*)&g_hc16[(size_t)r1 * DD + f] = __floats2half2_rn(x, y);
                s0 += x; s1 += y; q0 += x * x; q1 += y * y;
            }
            if (v2) {
                float x = c[nt][2] + b0, y = c[nt][3] + b1;
                *(__half2*)&g_hc16[(size_t)r2 * DD + f] = __floats2half2_rn(x, y);
                s0 += x; s1 += y; q0 += x * x; q1 += y * y;
            }
#pragma unroll
            for (int off = 4; off <= 16; off <<= 1) {
                s0 += __shfl_xor_sync(0xffffffffu, s0, off);
                s1 += __shfl_xor_sync(0xffffffffu, s1, off);
                q0 += __shfl_xor_sync(0xffffffffu, q0, off);
                q1 += __shfl_xor_sync(0xffffffffu, q1, off);
            }
            if (g == 0) {
                atomicAdd(&ssum[f], s0);     atomicAdd(&ssum[f + 1], s1);
                atomicAdd(&ssq[f], q0);      atomicAdd(&ssq[f + 1], q1);
            }
        }
    }
    __syncthreads();
    if (tid < DD) {
        atomicAdd(&stats[tid],      ssum[tid]);
        atomicAdd(&stats[DD + tid], ssq[tid]);
    }
}

// ---------------------------------------------------------------------------
// BN finalize + apply + leakyrelu + residual; write g_hs16 for next layer.
// gamma/beta loaded pre-wait (inputs).
__global__ void bn_apply_kernel(const float* __restrict__ gamma,
                                const float* __restrict__ beta,
                                const float* __restrict__ stats) {
    PDL_TRIGGER();
    __shared__ float sc[DD], sh[DD];
    int tid = threadIdx.x;
    float gm = 0.f, bt = 0.f;
    if (tid < DD) { gm = gamma[tid]; bt = beta[tid]; }
    PDL_WAIT();                               // need stats + hc16
    if (tid < DD) {
        float mean = stats[tid] * (1.f / NN);
        float ex2  = stats[DD + tid] * (1.f / NN);
        float inv  = rsqrtf(ex2 - mean * mean + 1e-5f);
        float s    = gm * inv;
        sc[tid] = s;
        sh[tid] = bt - mean * s;
    }
    __syncthreads();
#pragma unroll
    for (int u = 0; u < 2; u++) {
        int i = blockIdx.x * 512 + u * 256 + tid;   // over NN*16 float4s
        if (i >= NN * (DD / 4)) return;
        int n = i >> 4;
        int f0 = (i & 15) * 4;
        const __half2* cp = (const __half2*)&g_hc16[(size_t)i * 4];
        float2 c01 = __half22float2(cp[0]);
        float2 c23 = __half22float2(cp[1]);
        float4 h4 = ((const float4*)g_h)[i];
        float ns = g_norm_src[n];
        float v;
        v = c01.x * sc[f0 + 0] + sh[f0 + 0]; h4.x += (v >= 0.f) ? v : 0.2f * v;
        v = c01.y * sc[f0 + 1] + sh[f0 + 1]; h4.y += (v >= 0.f) ? v : 0.2f * v;
        v = c23.x * sc[f0 + 2] + sh[f0 + 2]; h4.z += (v >= 0.f) ? v : 0.2f * v;
        v = c23.y * sc[f0 + 3] + sh[f0 + 3]; h4.w += (v >= 0.f) ? v : 0.2f * v;
        ((float4*)g_h)[i] = h4;
        __half2* hp = (__half2*)&g_hs16[(size_t)i * 4];
        hp[0] = __floats2half2_rn(h4.x * ns, h4.y * ns);
        hp[1] = __floats2half2_rn(h4.z * ns, h4.w * ns);
    }
}

// ---------------------------------------------------------------------------
// Final fused kernel: BN(l=3)+leaky+residual, logits + log_softmax.
// Ws/bs staged pre-wait (inputs).
__global__ void __launch_bounds__(256) out_kernel(
        const float* __restrict__ gamma, const float* __restrict__ beta,
        const float* __restrict__ stats,
        const float* __restrict__ W, const float* __restrict__ b,
        float* __restrict__ out) {
    PDL_TRIGGER();
    __shared__ float Ws[DD * NC];   // 10 KB
    __shared__ float bs[NC];
    __shared__ float sc[DD], sh[DD];
    __shared__ float hrow[8][DD];
    int tid = threadIdx.x;          // 256 threads = 8 warps
    for (int i = tid; i < DD * NC; i += 256) Ws[i] = W[i];
    if (tid < NC) bs[tid] = b[tid];
    float gm = 0.f, bt = 0.f;
    if (tid < DD) { gm = gamma[tid]; bt = beta[tid]; }
    PDL_WAIT();                               // need stats + hc16 + h
    if (tid < DD) {
        float mean = stats[tid] * (1.f / NN);
        float ex2  = stats[DD + tid] * (1.f / NN);
        float inv  = rsqrtf(ex2 - mean * mean + 1e-5f);
        float s    = gm * inv;
        sc[tid] = s;
        sh[tid] = bt - mean * s;
    }
    __syncthreads();
    int warp = tid >> 5, lane = tid & 31;
    int n = blockIdx.x * 8 + warp;  // NN divisible by 8
    if (n >= NN) return;
    {
        int f = lane * 2;
        float2 c  = __half22float2(*(const __half2*)&g_hc16[(size_t)n * DD + f]);
        float2 h2 = *(const float2*)&g_h[(size_t)n * DD + f];
        float v;
        v = c.x * sc[f]     + sh[f];     h2.x += (v >= 0.f) ? v : 0.2f * v;
        v = c.y * sc[f + 1] + sh[f + 1]; h2.y += (v >= 0.f) ? v : 0.2f * v;
        hrow[warp][f]     = h2.x;
        hrow[warp][f + 1] = h2.y;
    }
    __syncwarp();
    int c0 = lane, c1 = lane + 32;
    bool has1 = (c1 < NC);
    float acc0 = bs[c0];
    float acc1 = has1 ? bs[c1] : 0.f;
#pragma unroll
    for (int k = 0; k < DD; k++) {
        float hv = hrow[warp][k];
        acc0 += hv * Ws[k * NC + c0];
        if (has1) acc1 += hv * Ws[k * NC + c1];
    }
    float m = has1 ? fmaxf(acc0, acc1) : acc0;
#pragma unroll
    for (int off = 16; off; off >>= 1) m = fmaxf(m, __shfl_xor_sync(0xffffffffu, m, off));
    float e = expf(acc0 - m) + (has1 ? expf(acc1 - m) : 0.f);
#pragma unroll
    for (int off = 16; off; off >>= 1) e += __shfl_xor_sync(0xffffffffu, e, off);
    float ls = m + logf(e);
    out[(size_t)n * NC + c0] = acc0 - ls;
    if (has1) out[(size_t)n * NC + c1] = acc1 - ls;
}

// ---------------------------------------------------------------------------
extern "C" void kernel_launch(void* const* d_in, const int* in_sizes, int n_in,
                              void* d_out, int out_size) {
    const float* V     = (const float*)d_in[0];
    const int*   src   = (const int*)d_in[1];
    const int*   dst   = (const int*)d_in[2];
    const float* W_in  = (const float*)d_in[3];
    const float* b_in  = (const float*)d_in[4];
    const float* W_l   = (const float*)d_in[5];
    const float* b_l   = (const float*)d_in[6];
    const float* gamma = (const float*)d_in[7];
    const float* beta  = (const float*)d_in[8];
    const float* W_out = (const float*)d_in[9];
    const float* b_out = (const float*)d_in[10];
    float* out = (float*)d_out;

    float* stats_base;
    cudaGetSymbolAddress((void**)&stats_base, g_stats);

    cudaLaunchAttribute attr;
    attr.id = cudaLaunchAttributeProgrammaticStreamSerialization;
    attr.val.programmaticStreamSerializationAllowed = 1;

    auto cfg = [&](int grid) {
        cudaLaunchConfig_t c = {};
        c.gridDim = dim3(grid);
        c.blockDim = dim3(256);
        c.dynamicSmemBytes = 0;
        c.stream = 0;
        c.attrs = &attr;
        c.numAttrs = 1;
        return c;
    };

    cudaLaunchConfig_t c;
    c = cfg((NE + 255) / 256);
    cudaLaunchKernelEx(&c, deg_kernel, src, dst);
    c = cfg(NSB);
    cudaLaunchKernelEx(&c, offsets_kernel);
    c = cfg((NE + 255) / 256);
    cudaLaunchKernelEx(&c, fill_kernel, src, dst);

    c = cfg((NTILE + TPB - 1) / TPB);
    cudaLaunchKernelEx(&c, input_gemm_tc, V, W_in, b_in);

    for (int l = 0; l < NLAY; l++) {
        float* stats = stats_base + (size_t)l * 2 * DD;
        c = cfg(NN / 8);
        cudaLaunchKernelEx(&c, gather_kernel, stats);
        c = cfg((NTILE + TPB - 1) / TPB);
        const float* Wl = W_l + (size_t)l * DD * DD;
        const float* bl = b_l + (size_t)l * DD;
        cudaLaunchKernelEx(&c, gemm_bn_tc, Wl, bl, stats);
        if (l < NLAY - 1) {
            c = cfg((NN * (DD / 4) + 511) / 512);
            const float* gl = gamma + (size_t)l * DD;
            const float* btl = beta + (size_t)l * DD;
            cudaLaunchKernelEx(&c, bn_apply_kernel, gl, btl,
                               (const float*)stats);
        }
    }

    c = cfg(NN / 8);
    cudaLaunchKernelEx(&c, out_kernel,
                       (const float*)(gamma + (size_t)(NLAY - 1) * DD),
                       (const float*)(beta + (size_t)(NLAY - 1) * DD),
                       (const float*)(stats_base + (size_t)(NLAY - 1) * 2 * DD),
                       W_out, b_out, out);
}